// round 4
// baseline (speedup 1.0000x reference)
#include <cuda_runtime.h>
#include <math.h>

// Problem constants
#define N    1024
#define P    8
#define D    2048
#define SEG  9                 // 1 global + 8 parts
#define KTOT (SEG * D)         // 18432
#define MARGIN 0.3f

// GEMM tiling
#define BM 64
#define BK 32
#define NBLK (N / BM)                      // 16 block-rows
#define NTRI (NBLK * (NBLK + 1) / 2)       // 136 triangle blocks

// Scratch (device globals: allocation-free rule)
__device__ float    g_F[(size_t)N * KTOT];   // packed & normalized features [N][KTOT]
__device__ float    g_S[(size_t)N * N];      // gram matrix S = F F^T
__device__ float    g_rowloss[N];
__device__ unsigned g_mask[N];               // 8-bit part-presence mask per row
__device__ int      g_lbl_stride;            // 1 = int32 labels, 2 = int64 labels

// Packed f32x2 FMA (Blackwell FFMA2 — ptxas never auto-fuses; PTX-only path)
__device__ __forceinline__ void ffma2(unsigned long long& acc,
                                      unsigned long long a2,
                                      unsigned long long b2) {
    asm("fma.rn.f32x2 %0, %1, %2, %0;" : "+l"(acc) : "l"(a2), "l"(b2));
}
__device__ __forceinline__ unsigned long long bcast2(unsigned x) {
    unsigned long long r;
    asm("mov.b64 %0, {%1, %1};" : "=l"(r) : "r"(x));
    return r;
}

// ---------------------------------------------------------------------------
// Kernel 1: per-(row, segment) L2 normalize and pack into F.
// ---------------------------------------------------------------------------
__global__ void k_normalize(const float* __restrict__ gf,
                            const float* __restrict__ pf,
                            const float* __restrict__ pl) {
    int b = blockIdx.x;                  // 0 .. N*SEG-1
    int i = b / SEG;
    int s = b % SEG;
    const float* src = (s == 0) ? (gf + (size_t)i * D)
                                : (pf + ((size_t)i * P + (s - 1)) * D);

    float ss = 0.f;
    for (int t = threadIdx.x; t < D; t += blockDim.x) {
        float v = src[t];
        ss += v * v;
    }
    __shared__ float red[8];
    #pragma unroll
    for (int o = 16; o; o >>= 1) ss += __shfl_xor_sync(0xffffffffu, ss, o);
    if ((threadIdx.x & 31) == 0) red[threadIdx.x >> 5] = ss;
    __syncthreads();
    if (threadIdx.x < 8) {
        float v = red[threadIdx.x];
        #pragma unroll
        for (int o = 4; o; o >>= 1) v += __shfl_xor_sync(0xffu, v, o);
        if (threadIdx.x == 0) red[0] = v;
    }
    __syncthreads();

    float scale = 1.f / (sqrtf(red[0]) + 1e-12f);
    if (s > 0) scale *= pl[(size_t)i * P + (s - 1)];   // zero-out absent parts

    float* dst = g_F + (size_t)i * KTOT + (size_t)s * D;
    for (int t = threadIdx.x; t < D; t += blockDim.x)
        dst[t] = src[t] * scale;
}

// ---------------------------------------------------------------------------
// Kernel 2: pack part-label bitmasks (labels are exactly 0.0 / 1.0)
// ---------------------------------------------------------------------------
__global__ void k_pack_mask(const float* __restrict__ pl) {
    int i = blockIdx.x * blockDim.x + threadIdx.x;
    if (i < N) {
        unsigned m = 0;
        #pragma unroll
        for (int k = 0; k < P; k++)
            if (pl[(size_t)i * P + k] != 0.f) m |= (1u << k);
        g_mask[i] = m;
    }
}

// ---------------------------------------------------------------------------
// Kernel 3: detect label dtype layout (int64 high words are all zero).
// ---------------------------------------------------------------------------
__global__ void k_detect_labels(const int* __restrict__ lbl) {
    __shared__ int any;
    if (threadIdx.x == 0) any = 0;
    __syncthreads();
    int v = 0;
    for (int j = 1 + 2 * threadIdx.x; j < N; j += 2 * blockDim.x)
        v |= lbl[j];
    if (v) atomicOr(&any, 1);
    __syncthreads();
    if (threadIdx.x == 0) g_lbl_stride = any ? 1 : 2;
}

// ---------------------------------------------------------------------------
// Kernel 4: symmetric SGEMM S = F F^T, lower-triangle blocks only.
// 64x64 tile, BK=32, 256 threads, 4x4 micro-tile done as 4 rows x 2 col-pairs
// with packed fma.rn.f32x2 (FFMA2): 8 FFMA2 + 8 MOV per kk vs 16 FFMA.
// ---------------------------------------------------------------------------
__global__ void __launch_bounds__(256, 1) k_gemm() {
    __shared__ float As[BK][BM + 4];   // row stride 68 floats = 272B = 17*16B (16B-aligned)
    __shared__ float Bs[BK][BM + 4];

    int bid = blockIdx.x;
    int bi = (int)((sqrtf(8.f * (float)bid + 1.f) - 1.f) * 0.5f);
    while ((bi + 1) * (bi + 2) / 2 <= bid) bi++;
    while (bi * (bi + 1) / 2 > bid) bi--;
    int bj = bid - bi * (bi + 1) / 2;     // bj <= bi

    int tid = threadIdx.x;
    int ty = tid >> 4;        // 0..15 : row group (4 rows each)
    int tx = tid & 15;        // 0..15 : col group (4 cols = 2 pairs each)

    unsigned long long acc[4][2] = {};    // packed {col0,col1} fp32 pairs, = {0.f,0.f}

    const float* Fa = g_F + (size_t)(bi * BM) * KTOT;
    const float* Fb = g_F + (size_t)(bj * BM) * KTOT;

    int f0row = tid >> 3;           // 0..31
    int f0kq  = tid & 7;            // 0..7
    int f1row = (tid + 256) >> 3;   // 32..63

    for (int k0 = 0; k0 < KTOT; k0 += BK) {
        float4 va0 = *(const float4*)(Fa + (size_t)f0row * KTOT + k0 + f0kq * 4);
        float4 vb0 = *(const float4*)(Fb + (size_t)f0row * KTOT + k0 + f0kq * 4);
        float4 va1 = *(const float4*)(Fa + (size_t)f1row * KTOT + k0 + f0kq * 4);
        float4 vb1 = *(const float4*)(Fb + (size_t)f1row * KTOT + k0 + f0kq * 4);

        As[f0kq * 4 + 0][f0row] = va0.x;  As[f0kq * 4 + 1][f0row] = va0.y;
        As[f0kq * 4 + 2][f0row] = va0.z;  As[f0kq * 4 + 3][f0row] = va0.w;
        Bs[f0kq * 4 + 0][f0row] = vb0.x;  Bs[f0kq * 4 + 1][f0row] = vb0.y;
        Bs[f0kq * 4 + 2][f0row] = vb0.z;  Bs[f0kq * 4 + 3][f0row] = vb0.w;
        As[f0kq * 4 + 0][f1row] = va1.x;  As[f0kq * 4 + 1][f1row] = va1.y;
        As[f0kq * 4 + 2][f1row] = va1.z;  As[f0kq * 4 + 3][f1row] = va1.w;
        Bs[f0kq * 4 + 0][f1row] = vb1.x;  Bs[f0kq * 4 + 1][f1row] = vb1.y;
        Bs[f0kq * 4 + 2][f1row] = vb1.z;  Bs[f0kq * 4 + 3][f1row] = vb1.w;
        __syncthreads();

        #pragma unroll
        for (int kk = 0; kk < BK; kk++) {
            uint4 a = *(const uint4*)&As[kk][ty * 4];                 // 4 A rows (bits)
            ulonglong2 b = *(const ulonglong2*)&Bs[kk][tx * 4];       // 2 packed B col-pairs

            unsigned long long a0 = bcast2(a.x);
            unsigned long long a1 = bcast2(a.y);
            unsigned long long a2 = bcast2(a.z);
            unsigned long long a3 = bcast2(a.w);

            ffma2(acc[0][0], a0, b.x);  ffma2(acc[0][1], a0, b.y);
            ffma2(acc[1][0], a1, b.x);  ffma2(acc[1][1], a1, b.y);
            ffma2(acc[2][0], a2, b.x);  ffma2(acc[2][1], a2, b.y);
            ffma2(acc[3][0], a3, b.x);  ffma2(acc[3][1], a3, b.y);
        }
        __syncthreads();
    }

    #pragma unroll
    for (int r = 0; r < 4; r++) {
        #pragma unroll
        for (int cp = 0; cp < 2; cp++) {
            int gi = bi * BM + ty * 4 + r;
            int gj = bj * BM + tx * 4 + cp * 2;
            float vlo = __uint_as_float((unsigned)(acc[r][cp]));         // col gj
            float vhi = __uint_as_float((unsigned)(acc[r][cp] >> 32));   // col gj+1
            g_S[(size_t)gi * N + gj]     = vlo;
            g_S[(size_t)gi * N + gj + 1] = vhi;
            g_S[(size_t)gj * N + gi]       = vlo;   // mirror
            g_S[(size_t)(gj + 1) * N + gi] = vhi;
        }
    }
}

// ---------------------------------------------------------------------------
// Kernel 5: hard mining per row.
// dist[i,j] = 0.5 - S[i,j] / (2*(O[i,j]+1)),  O = popc(mask_i & mask_j)
// ---------------------------------------------------------------------------
__global__ void k_mine(const int* __restrict__ lbl) {
    int i = blockIdx.x;
    int stride = g_lbl_stride;
    int li = lbl[(size_t)i * stride];
    unsigned mi = g_mask[i];

    float ap = -1e30f, an = 1e30f;
    for (int j = threadIdx.x; j < N; j += blockDim.x) {
        float s = g_S[(size_t)i * N + j];
        float o = (float)__popc(mi & g_mask[j]);
        float dist = 0.5f - s / (2.f * (o + 1.f));
        if (lbl[(size_t)j * stride] == li) ap = fmaxf(ap, dist);
        else                               an = fminf(an, dist);
    }

    __shared__ float sap[256], san[256];
    sap[threadIdx.x] = ap;
    san[threadIdx.x] = an;
    __syncthreads();
    for (int o = 128; o; o >>= 1) {
        if (threadIdx.x < o) {
            sap[threadIdx.x] = fmaxf(sap[threadIdx.x], sap[threadIdx.x + o]);
            san[threadIdx.x] = fminf(san[threadIdx.x], san[threadIdx.x + o]);
        }
        __syncthreads();
    }
    if (threadIdx.x == 0)
        g_rowloss[i] = fmaxf(0.f, sap[0] - san[0] + MARGIN);
}

// ---------------------------------------------------------------------------
// Kernel 6: final mean
// ---------------------------------------------------------------------------
__global__ void k_final(float* __restrict__ out) {
    float s = 0.f;
    for (int j = threadIdx.x; j < N; j += blockDim.x)
        s += g_rowloss[j];
    __shared__ float red[8];
    #pragma unroll
    for (int o = 16; o; o >>= 1) s += __shfl_xor_sync(0xffffffffu, s, o);
    if ((threadIdx.x & 31) == 0) red[threadIdx.x >> 5] = s;
    __syncthreads();
    if (threadIdx.x == 0) {
        float t = 0.f;
        #pragma unroll
        for (int w = 0; w < 8; w++) t += red[w];
        out[0] = t / (float)N;
    }
}

// ---------------------------------------------------------------------------
extern "C" void kernel_launch(void* const* d_in, const int* in_sizes, int n_in,
                              void* d_out, int out_size) {
    const float* gf  = (const float*)d_in[0];   // global_feat  [N, D]
    const float* pf  = (const float*)d_in[1];   // partial_feat [N, P, D]
    const float* pl  = (const float*)d_in[2];   // part_labels  [N, P]
    const int*   lbl = (const int*)d_in[3];     // global_labels (int32 or int64)
    float* out = (float*)d_out;

    k_normalize<<<N * SEG, 256>>>(gf, pf, pl);
    k_pack_mask<<<(N + 255) / 256, 256>>>(pl);
    k_detect_labels<<<1, 256>>>(lbl);
    k_gemm<<<NTRI, 256>>>();
    k_mine<<<N, 256>>>(lbl);
    k_final<<<1, 256>>>(out);
}

// round 6
// speedup vs baseline: 10.4381x; 10.4381x over previous
#include <cuda_runtime.h>
#include <cuda_fp16.h>
#include <math.h>
#include <stdint.h>

// Problem constants
#define N    1024
#define P    8
#define D    2048
#define SEG  9                 // 1 global + 8 parts
#define KTOT (SEG * D)         // 18432
#define MARGIN 0.3f

// GEMM tiling
#define TM   128
#define TN   128
#define TK   64                // K elements per smem chunk (128B fp16 rows)
#define NBLK (N / TM)          // 8
#define NPAIR (NBLK * (NBLK + 1) / 2)   // 36 triangle pairs
#define KSPLIT 4
#define KPER  (KTOT / KSPLIT)  // 4608
#define NCHUNK (KPER / TK)     // 72

// smem: A tile 128x64 fp16 (16KB, swizzled) + B tile (16KB), double buffered
#define TILE_B  (TM * TK * 2)          // 16384
#define BUF_B   (2 * TILE_B)           // 32768
#define SMEM_TOTAL (2 * BUF_B)         // 65536

// Scratch (device globals: allocation-free rule)
__device__ __half    g_Hf[(size_t)N * KTOT];                  // fp16 features
__device__ float     g_P1[(size_t)KSPLIT * NPAIR * TM * TN];  // GEMM partials
__device__ float     g_S[(size_t)N * N];
__device__ float     g_rowloss[N];
__device__ unsigned  g_mask[N];
__device__ int       g_lbl_stride;   // 1 = int32 labels, 2 = int64 labels

// ---------------------------------------------------------------------------
// PTX helpers (sm_80-era: valid on plain compute_103 target)
// ---------------------------------------------------------------------------
__device__ __forceinline__ uint32_t smem_u32(const void* p) {
    uint32_t a;
    asm("{ .reg .u64 t; cvta.to.shared.u64 t, %1; cvt.u32.u64 %0, t; }" : "=r"(a) : "l"(p));
    return a;
}
#define LDSM_X4(r0, r1, r2, r3, addr) \
    asm volatile("ldmatrix.sync.aligned.m8n8.x4.shared.b16 {%0,%1,%2,%3}, [%4];" \
        : "=r"(r0), "=r"(r1), "=r"(r2), "=r"(r3) : "r"(addr))
#define MMA16816(d, a0, a1, a2, a3, b0, b1) \
    asm volatile("mma.sync.aligned.m16n8k16.row.col.f32.f16.f16.f32 " \
        "{%0,%1,%2,%3}, {%4,%5,%6,%7}, {%8,%9}, {%0,%1,%2,%3};" \
        : "+f"((d)[0]), "+f"((d)[1]), "+f"((d)[2]), "+f"((d)[3]) \
        : "r"(a0), "r"(a1), "r"(a2), "r"(a3), "r"(b0), "r"(b1))

// ---------------------------------------------------------------------------
// Kernel 1: single-pass normalize + fp16 pack (8 values/thread in regs)
// ---------------------------------------------------------------------------
__global__ void k_normalize(const float* __restrict__ gf,
                            const float* __restrict__ pf,
                            const float* __restrict__ pl) {
    int b = blockIdx.x;                  // 0 .. N*SEG-1
    int i = b / SEG;
    int s = b % SEG;
    const float* src = (s == 0) ? (gf + (size_t)i * D)
                                : (pf + ((size_t)i * P + (s - 1)) * D);

    float vals[8];
    float ss = 0.f;
    #pragma unroll
    for (int u = 0; u < 8; u++) {
        float v = src[threadIdx.x + 256 * u];
        vals[u] = v;
        ss += v * v;
    }
    __shared__ float red[8];
    #pragma unroll
    for (int o = 16; o; o >>= 1) ss += __shfl_xor_sync(0xffffffffu, ss, o);
    if ((threadIdx.x & 31) == 0) red[threadIdx.x >> 5] = ss;
    __syncthreads();
    if (threadIdx.x < 8) {
        float v = red[threadIdx.x];
        #pragma unroll
        for (int o = 4; o; o >>= 1) v += __shfl_xor_sync(0xffu, v, o);
        if (threadIdx.x == 0) red[0] = v;
    }
    __syncthreads();

    float scale = 1.f / (sqrtf(red[0]) + 1e-12f);
    if (s > 0) scale *= pl[(size_t)i * P + (s - 1)];

    __half* dst = g_Hf + (size_t)i * KTOT + (size_t)s * D;
    #pragma unroll
    for (int u = 0; u < 8; u++)
        dst[threadIdx.x + 256 * u] = __float2half(vals[u] * scale);
}

// ---------------------------------------------------------------------------
// Kernel 2: pack part-label bitmasks
// ---------------------------------------------------------------------------
__global__ void k_pack_mask(const float* __restrict__ pl) {
    int i = blockIdx.x * blockDim.x + threadIdx.x;
    if (i < N) {
        unsigned m = 0;
        #pragma unroll
        for (int k = 0; k < P; k++)
            if (pl[(size_t)i * P + k] != 0.f) m |= (1u << k);
        g_mask[i] = m;
    }
}

// ---------------------------------------------------------------------------
// Kernel 3: detect label dtype layout (int64 high words are all zero)
// ---------------------------------------------------------------------------
__global__ void k_detect_labels(const int* __restrict__ lbl) {
    __shared__ int any;
    if (threadIdx.x == 0) any = 0;
    __syncthreads();
    int v = 0;
    for (int j = 1 + 2 * threadIdx.x; j < N; j += 2 * blockDim.x)
        v |= lbl[j];
    if (v) atomicOr(&any, 1);
    __syncthreads();
    if (threadIdx.x == 0) g_lbl_stride = any ? 1 : 2;
}

// ---------------------------------------------------------------------------
// Kernel 4: HMMA fp16 GEMM, triangle 128x128 tiles, K-split x4.
// 8 warps (2x4), warp tile 64x32, m16n8k16, double-buffered swizzled smem.
// ---------------------------------------------------------------------------
__global__ void __launch_bounds__(256, 1) k_gemm_mma() {
    extern __shared__ char smem[];
    uint32_t sbase = smem_u32(smem);

    int tid  = threadIdx.x;
    int lane = tid & 31;
    int wid  = tid >> 5;
    int wm   = wid >> 2;      // 0..1  (M warp row)
    int wn   = wid & 3;       // 0..3  (N warp col)

    // triangle pair decode
    int pid = blockIdx.x;
    int bi = (int)((sqrtf(8.f * (float)pid + 1.f) - 1.f) * 0.5f);
    while ((bi + 1) * (bi + 2) / 2 <= pid) bi++;
    while (bi * (bi + 1) / 2 > pid) bi--;
    int bj = pid - bi * (bi + 1) / 2;     // bj <= bi
    int kbase = blockIdx.y * KPER;

    const __half* Fa = g_Hf + (size_t)(bi * TM) * KTOT;
    const __half* Fb = g_Hf + (size_t)(bj * TM) * KTOT;

    // ldmatrix address precompute (buffer-0 A base = sbase, B base = sbase+TILE_B)
    // A frags f=0..3: row = wm*64 + f*16 + (lane&15), chunk-half = lane>>4
    uint32_t aRowOff[4]; uint32_t aR7[4];
    #pragma unroll
    for (int f = 0; f < 4; f++) {
        int r = wm * 64 + f * 16 + (lane & 15);
        aRowOff[f] = sbase + (uint32_t)(r * 128);
        aR7[f] = (uint32_t)(r & 7);
    }
    uint32_t aHalf = (uint32_t)(lane >> 4);          // 0/1 -> +chunk
    // B frag-pairs gp=0..1: n = wn*32 + gp*16 + ((lane>>4)<<3) + (lane&7)
    uint32_t bRowOff[2]; uint32_t bR7[2];
    #pragma unroll
    for (int gp = 0; gp < 2; gp++) {
        int n = wn * 32 + gp * 16 + ((lane >> 4) << 3) + (lane & 7);
        bRowOff[gp] = sbase + TILE_B + (uint32_t)(n * 128);
        bR7[gp] = (uint32_t)(n & 7);
    }
    uint32_t bHalf = (uint32_t)((lane >> 3) & 1);

    // global prefetch mapping: q=0..7, v = tid+256q; r=(v>>3)&127, c=v&7
    // A for q<4, B for q>=4. smem store swizzled: off = r*128 + ((c^(r&7))<<4)
    int pr[8], pc[8]; uint32_t pso[8];
    #pragma unroll
    for (int q = 0; q < 8; q++) {
        int v = tid + 256 * q;
        pr[q] = (v >> 3) & 127;
        pc[q] = v & 7;
        pso[q] = (uint32_t)(((q & 4) ? TILE_B : 0) +
                            pr[q] * 128 + ((pc[q] ^ (pr[q] & 7)) << 4));
    }

    float acc[4][4][4];
    #pragma unroll
    for (int i = 0; i < 4; i++)
        #pragma unroll
        for (int j = 0; j < 4; j++)
            #pragma unroll
            for (int e = 0; e < 4; e++) acc[i][j][e] = 0.f;

    uint4 pre[8];

    // prologue: load chunk 0 into buffer 0
    #pragma unroll
    for (int q = 0; q < 8; q++) {
        const __half* src = (q < 4) ? Fa : Fb;
        pre[q] = *(const uint4*)(src + (size_t)pr[q] * KTOT + kbase + pc[q] * 8);
    }
    #pragma unroll
    for (int q = 0; q < 8; q++)
        *(uint4*)(smem + pso[q]) = pre[q];
    __syncthreads();

    for (int t = 0; t < NCHUNK; t++) {
        // prefetch next chunk
        if (t + 1 < NCHUNK) {
            int k0 = kbase + (t + 1) * TK;
            #pragma unroll
            for (int q = 0; q < 8; q++) {
                const __half* src = (q < 4) ? Fa : Fb;
                pre[q] = *(const uint4*)(src + (size_t)pr[q] * KTOT + k0 + pc[q] * 8);
            }
        }

        uint32_t boff = (uint32_t)((t & 1) * BUF_B);
        #pragma unroll
        for (int s = 0; s < 4; s++) {              // 4 k16 steps per chunk
            uint32_t a0, a1, a2, a3;
            uint32_t af[4][4];
            #pragma unroll
            for (int f = 0; f < 4; f++) {
                uint32_t c = 2u * s + aHalf;
                uint32_t ad = aRowOff[f] + boff + (((c ^ aR7[f])) << 4);
                LDSM_X4(af[f][0], af[f][1], af[f][2], af[f][3], ad);
            }
            uint32_t bf[4][2];
            #pragma unroll
            for (int gp = 0; gp < 2; gp++) {
                uint32_t c = 2u * s + bHalf;
                uint32_t bd = bRowOff[gp] + boff + (((c ^ bR7[gp])) << 4);
                uint32_t r0, r1, r2, r3;
                LDSM_X4(r0, r1, r2, r3, bd);
                bf[gp * 2][0] = r0;     bf[gp * 2][1] = r1;
                bf[gp * 2 + 1][0] = r2; bf[gp * 2 + 1][1] = r3;
            }
            #pragma unroll
            for (int f = 0; f < 4; f++)
                #pragma unroll
                for (int g = 0; g < 4; g++)
                    MMA16816(acc[f][g], af[f][0], af[f][1], af[f][2], af[f][3],
                             bf[g][0], bf[g][1]);
        }

        if (t + 1 < NCHUNK) {
            uint32_t nb = (uint32_t)(((t + 1) & 1) * BUF_B);
            #pragma unroll
            for (int q = 0; q < 8; q++)
                *(uint4*)(smem + nb + pso[q]) = pre[q];
        }
        __syncthreads();
    }

    // epilogue: store partials. c-frag mapping: rows lane>>2 (+8), cols 2*(lane&3)
    size_t pb = ((size_t)blockIdx.y * NPAIR + pid) * (size_t)(TM * TN);
    #pragma unroll
    for (int f = 0; f < 4; f++) {
        #pragma unroll
        for (int g = 0; g < 4; g++) {
            int row = wm * 64 + f * 16 + (lane >> 2);
            int col = wn * 32 + g * 8 + 2 * (lane & 3);
            *(float2*)&g_P1[pb + (size_t)row * TN + col] =
                make_float2(acc[f][g][0], acc[f][g][1]);
            *(float2*)&g_P1[pb + (size_t)(row + 8) * TN + col] =
                make_float2(acc[f][g][2], acc[f][g][3]);
        }
    }
}

// ---------------------------------------------------------------------------
// Kernel 5: assemble S from partials (sum K-splits, mirror)
// ---------------------------------------------------------------------------
__global__ void k_assemble() {
    int pid = blockIdx.x;
    int bi = (int)((sqrtf(8.f * (float)pid + 1.f) - 1.f) * 0.5f);
    while ((bi + 1) * (bi + 2) / 2 <= pid) bi++;
    while (bi * (bi + 1) / 2 > pid) bi--;
    int bj = pid - bi * (bi + 1) / 2;

    for (int e = threadIdx.x; e < TM * TN; e += blockDim.x) {
        float s = 0.f;
        #pragma unroll
        for (int ks = 0; ks < KSPLIT; ks++)
            s += g_P1[((size_t)ks * NPAIR + pid) * (size_t)(TM * TN) + e];
        int m = e >> 7, c = e & 127;
        int gi = bi * TM + m, gj = bj * TM + c;
        g_S[(size_t)gi * N + gj] = s;
        g_S[(size_t)gj * N + gi] = s;
    }
}

// ---------------------------------------------------------------------------
// Kernel 6: hard mining per row.
// dist[i,j] = 0.5 - S[i,j] / (2*(O[i,j]+1)),  O = popc(mask_i & mask_j)
// ---------------------------------------------------------------------------
__global__ void k_mine(const int* __restrict__ lbl) {
    int i = blockIdx.x;
    int stride = g_lbl_stride;
    int li = lbl[(size_t)i * stride];
    unsigned mi = g_mask[i];

    float ap = -1e30f, an = 1e30f;
    for (int j = threadIdx.x; j < N; j += blockDim.x) {
        float s = g_S[(size_t)i * N + j];
        float o = (float)__popc(mi & g_mask[j]);
        float dist = 0.5f - s / (2.f * (o + 1.f));
        if (lbl[(size_t)j * stride] == li) ap = fmaxf(ap, dist);
        else                               an = fminf(an, dist);
    }

    __shared__ float sap[256], san[256];
    sap[threadIdx.x] = ap;
    san[threadIdx.x] = an;
    __syncthreads();
    for (int o = 128; o; o >>= 1) {
        if (threadIdx.x < o) {
            sap[threadIdx.x] = fmaxf(sap[threadIdx.x], sap[threadIdx.x + o]);
            san[threadIdx.x] = fminf(san[threadIdx.x], san[threadIdx.x + o]);
        }
        __syncthreads();
    }
    if (threadIdx.x == 0)
        g_rowloss[i] = fmaxf(0.f, sap[0] - san[0] + MARGIN);
}

// ---------------------------------------------------------------------------
// Kernel 7: final mean
// ---------------------------------------------------------------------------
__global__ void k_final(float* __restrict__ out) {
    float s = 0.f;
    for (int j = threadIdx.x; j < N; j += blockDim.x)
        s += g_rowloss[j];
    __shared__ float red[8];
    #pragma unroll
    for (int o = 16; o; o >>= 1) s += __shfl_xor_sync(0xffffffffu, s, o);
    if ((threadIdx.x & 31) == 0) red[threadIdx.x >> 5] = s;
    __syncthreads();
    if (threadIdx.x == 0) {
        float t = 0.f;
        #pragma unroll
        for (int w = 0; w < 8; w++) t += red[w];
        out[0] = t / (float)N;
    }
}

// ---------------------------------------------------------------------------
extern "C" void kernel_launch(void* const* d_in, const int* in_sizes, int n_in,
                              void* d_out, int out_size) {
    const float* gf  = (const float*)d_in[0];   // global_feat  [N, D]
    const float* pf  = (const float*)d_in[1];   // partial_feat [N, P, D]
    const float* pl  = (const float*)d_in[2];   // part_labels  [N, P]
    const int*   lbl = (const int*)d_in[3];     // global_labels (int32 or int64)
    float* out = (float*)d_out;

    static int smem_set = 0;
    if (!smem_set) {
        cudaFuncSetAttribute(k_gemm_mma, cudaFuncAttributeMaxDynamicSharedMemorySize,
                             SMEM_TOTAL);
        smem_set = 1;
    }

    k_normalize<<<N * SEG, 256>>>(gf, pf, pl);
    k_pack_mask<<<(N + 255) / 256, 256>>>(pl);
    k_detect_labels<<<1, 256>>>(lbl);
    k_gemm_mma<<<dim3(NPAIR, KSPLIT), 256, SMEM_TOTAL>>>();
    k_assemble<<<NPAIR, 256>>>();
    k_mine<<<N, 256>>>(lbl);
    k_final<<<1, 256>>>(out);
}

// round 7
// speedup vs baseline: 11.5235x; 1.1040x over previous
#include <cuda_runtime.h>
#include <cuda_fp16.h>
#include <math.h>
#include <stdint.h>

// Problem constants
#define N    1024
#define P    8
#define D    2048
#define SEG  9                 // 1 global + 8 parts
#define KTOT (SEG * D)         // 18432
#define MARGIN 0.3f

// GEMM tiling
#define TM   128
#define TN   128
#define TK   64                // K elements per smem chunk (128B fp16 rows)
#define NBLK (N / TM)          // 8
#define NPAIR (NBLK * (NBLK + 1) / 2)   // 36 triangle pairs
#define KSPLIT 8
#define KPER  (KTOT / KSPLIT)  // 2304
#define NCHUNK (KPER / TK)     // 36

// smem: per stage A tile (16KB) + B tile (16KB); 3 stages
#define TILE_B   (TM * TK * 2)         // 16384
#define STAGE_B  (2 * TILE_B)          // 32768
#define NSTAGE   3
#define SMEM_TOTAL (NSTAGE * STAGE_B)  // 98304

// Scratch (device globals: allocation-free rule)
__device__ __half    g_Hf[(size_t)N * KTOT];                  // fp16 features
__device__ float     g_P1[(size_t)KSPLIT * NPAIR * TM * TN];  // GEMM partials
__device__ float     g_S[(size_t)N * N];
__device__ float     g_rowloss[N];
__device__ unsigned  g_mask[N];
__device__ int       g_lbl_stride;   // 1 = int32 labels, 2 = int64 labels

// ---------------------------------------------------------------------------
// PTX helpers (sm_80-era: valid on plain compute_103 target)
// ---------------------------------------------------------------------------
__device__ __forceinline__ uint32_t smem_u32(const void* p) {
    uint32_t a;
    asm("{ .reg .u64 t; cvta.to.shared.u64 t, %1; cvt.u32.u64 %0, t; }" : "=r"(a) : "l"(p));
    return a;
}
#define LDSM_X4(r0, r1, r2, r3, addr) \
    asm volatile("ldmatrix.sync.aligned.m8n8.x4.shared.b16 {%0,%1,%2,%3}, [%4];" \
        : "=r"(r0), "=r"(r1), "=r"(r2), "=r"(r3) : "r"(addr))
#define MMA16816(d, a0, a1, a2, a3, b0, b1) \
    asm volatile("mma.sync.aligned.m16n8k16.row.col.f32.f16.f16.f32 " \
        "{%0,%1,%2,%3}, {%4,%5,%6,%7}, {%8,%9}, {%0,%1,%2,%3};" \
        : "+f"((d)[0]), "+f"((d)[1]), "+f"((d)[2]), "+f"((d)[3]) \
        : "r"(a0), "r"(a1), "r"(a2), "r"(a3), "r"(b0), "r"(b1))
#define CP_ASYNC16(dst, src) \
    asm volatile("cp.async.cg.shared.global [%0], [%1], 16;" :: "r"(dst), "l"(src))
#define CP_COMMIT() asm volatile("cp.async.commit_group;" ::: "memory")
#define CP_WAIT1()  asm volatile("cp.async.wait_group 1;" ::: "memory")

// ---------------------------------------------------------------------------
// Kernel 1: single-pass normalize + fp16 pack (8 values/thread in regs)
// ---------------------------------------------------------------------------
__global__ void k_normalize(const float* __restrict__ gf,
                            const float* __restrict__ pf,
                            const float* __restrict__ pl) {
    int b = blockIdx.x;                  // 0 .. N*SEG-1
    int i = b / SEG;
    int s = b % SEG;
    const float* src = (s == 0) ? (gf + (size_t)i * D)
                                : (pf + ((size_t)i * P + (s - 1)) * D);

    float vals[8];
    float ss = 0.f;
    #pragma unroll
    for (int u = 0; u < 8; u++) {
        float v = src[threadIdx.x + 256 * u];
        vals[u] = v;
        ss += v * v;
    }
    __shared__ float red[8];
    #pragma unroll
    for (int o = 16; o; o >>= 1) ss += __shfl_xor_sync(0xffffffffu, ss, o);
    if ((threadIdx.x & 31) == 0) red[threadIdx.x >> 5] = ss;
    __syncthreads();
    if (threadIdx.x < 8) {
        float v = red[threadIdx.x];
        #pragma unroll
        for (int o = 4; o; o >>= 1) v += __shfl_xor_sync(0xffu, v, o);
        if (threadIdx.x == 0) red[0] = v;
    }
    __syncthreads();

    float scale = 1.f / (sqrtf(red[0]) + 1e-12f);
    if (s > 0) scale *= pl[(size_t)i * P + (s - 1)];

    __half* dst = g_Hf + (size_t)i * KTOT + (size_t)s * D;
    #pragma unroll
    for (int u = 0; u < 8; u++)
        dst[threadIdx.x + 256 * u] = __float2half(vals[u] * scale);
}

// ---------------------------------------------------------------------------
// Kernel 2: meta — part-label bitmasks + label dtype detect (fused)
// ---------------------------------------------------------------------------
__global__ void k_meta(const float* __restrict__ pl, const int* __restrict__ lbl) {
    int i = blockIdx.x * blockDim.x + threadIdx.x;
    if (i < N) {
        unsigned m = 0;
        #pragma unroll
        for (int k = 0; k < P; k++)
            if (pl[(size_t)i * P + k] != 0.f) m |= (1u << k);
        g_mask[i] = m;
    }
    if (blockIdx.x == 0) {
        __shared__ int any;
        if (threadIdx.x == 0) any = 0;
        __syncthreads();
        int v = 0;
        for (int j = 1 + 2 * threadIdx.x; j < N; j += 2 * blockDim.x)
            v |= lbl[j];
        if (v) atomicOr(&any, 1);
        __syncthreads();
        if (threadIdx.x == 0) g_lbl_stride = any ? 1 : 2;
    }
}

// ---------------------------------------------------------------------------
// Kernel 3: HMMA fp16 GEMM, triangle 128x128 tiles, K-split x8.
// 8 warps (2x4), warp tile 64x32, m16n8k16, 3-stage cp.async pipeline.
// 2 CTAs/SM (regs<=128, 96KB smem/CTA).
// ---------------------------------------------------------------------------
__global__ void __launch_bounds__(256, 2) k_gemm_mma() {
    extern __shared__ char smem[];
    uint32_t sbase = smem_u32(smem);

    int tid  = threadIdx.x;
    int lane = tid & 31;
    int wid  = tid >> 5;
    int wm   = wid >> 2;      // 0..1  (M warp row)
    int wn   = wid & 3;       // 0..3  (N warp col)

    // triangle pair decode
    int pid = blockIdx.x;
    int bi = (int)((sqrtf(8.f * (float)pid + 1.f) - 1.f) * 0.5f);
    while ((bi + 1) * (bi + 2) / 2 <= pid) bi++;
    while (bi * (bi + 1) / 2 > pid) bi--;
    int bj = pid - bi * (bi + 1) / 2;     // bj <= bi
    int kbase = blockIdx.y * KPER;

    // cp.async source/dest mapping: per thread covers 4 rows (stride 32) of A
    // and 4 rows of B. r = tid>>3 (0..31), c16 = tid&7 (16B chunk).
    int rA  = tid >> 3;
    int c16 = tid & 7;
    const __half* srcA = g_Hf + (size_t)(bi * TM + rA) * KTOT + kbase + c16 * 8;
    const __half* srcB = g_Hf + (size_t)(bj * TM + rA) * KTOT + kbase + c16 * 8;
    // swizzled smem offset within tile; q-advance is +4096 (r+=32 keeps r&7)
    uint32_t pso = (uint32_t)(rA * 128 + ((c16 ^ (rA & 7)) << 4));

    // ldmatrix bases (within stage). Fragment row offsets are multiples of 8,
    // so the swizzle XOR operand is lane&7 for both A and B.
    uint32_t r7 = (uint32_t)(lane & 7);
    uint32_t aBase[4];
    #pragma unroll
    for (int f = 0; f < 4; f++)
        aBase[f] = sbase + (uint32_t)((wm * 64 + f * 16 + (lane & 15)) * 128);
    uint32_t aHalf = (uint32_t)(lane >> 4);
    uint32_t bBase[2];
    #pragma unroll
    for (int gp = 0; gp < 2; gp++)
        bBase[gp] = sbase + TILE_B +
            (uint32_t)((wn * 32 + gp * 16 + ((lane >> 4) << 3) + (lane & 7)) * 128);
    uint32_t bHalf = (uint32_t)((lane >> 3) & 1);

    float acc[4][4][4];
    #pragma unroll
    for (int i = 0; i < 4; i++)
        #pragma unroll
        for (int j = 0; j < 4; j++)
            #pragma unroll
            for (int e = 0; e < 4; e++) acc[i][j][e] = 0.f;

    // chunk issue: 4 A + 4 B cp.asyncs, stride KTOT*32 halfs in gmem, 4096B smem
    auto issue = [&](int t) {
        if (t < NCHUNK) {
            uint32_t st = (uint32_t)(t % NSTAGE) * STAGE_B;
            uint32_t dA = sbase + st + pso;
            uint32_t dB = dA + TILE_B;
            const __half* sA = srcA + (size_t)t * TK;
            const __half* sB = srcB + (size_t)t * TK;
            #pragma unroll
            for (int q = 0; q < 4; q++) {
                CP_ASYNC16(dA + q * 4096, sA + (size_t)q * 32 * KTOT);
                CP_ASYNC16(dB + q * 4096, sB + (size_t)q * 32 * KTOT);
            }
        }
        CP_COMMIT();
    };

    issue(0);
    issue(1);

    for (int t = 0; t < NCHUNK; t++) {
        CP_WAIT1();              // chunk t resident (<=1 group outstanding)
        __syncthreads();

        uint32_t boff = (uint32_t)(t % NSTAGE) * STAGE_B;
        #pragma unroll
        for (int s = 0; s < 4; s++) {              // 4 k16 steps per chunk
            uint32_t swA = ((2u * s + aHalf) ^ r7) << 4;
            uint32_t swB = ((2u * s + bHalf) ^ r7) << 4;
            uint32_t af[4][4];
            #pragma unroll
            for (int f = 0; f < 4; f++)
                LDSM_X4(af[f][0], af[f][1], af[f][2], af[f][3],
                        aBase[f] + boff + swA);
            uint32_t bf[4][2];
            #pragma unroll
            for (int gp = 0; gp < 2; gp++) {
                uint32_t r0, r1, r2, r3;
                LDSM_X4(r0, r1, r2, r3, bBase[gp] + boff + swB);
                bf[gp * 2][0] = r0;     bf[gp * 2][1] = r1;
                bf[gp * 2 + 1][0] = r2; bf[gp * 2 + 1][1] = r3;
            }
            #pragma unroll
            for (int f = 0; f < 4; f++)
                #pragma unroll
                for (int g = 0; g < 4; g++)
                    MMA16816(acc[f][g], af[f][0], af[f][1], af[f][2], af[f][3],
                             bf[g][0], bf[g][1]);
        }

        issue(t + 2);            // writes stage (t-1)%3, free since top sync
    }

    // epilogue: store partials. c-frag: rows lane>>2 (+8), cols 2*(lane&3)
    size_t pb = ((size_t)blockIdx.y * NPAIR + pid) * (size_t)(TM * TN);
    #pragma unroll
    for (int f = 0; f < 4; f++) {
        #pragma unroll
        for (int g = 0; g < 4; g++) {
            int row = wm * 64 + f * 16 + (lane >> 2);
            int col = wn * 32 + g * 8 + 2 * (lane & 3);
            *(float2*)&g_P1[pb + (size_t)row * TN + col] =
                make_float2(acc[f][g][0], acc[f][g][1]);
            *(float2*)&g_P1[pb + (size_t)(row + 8) * TN + col] =
                make_float2(acc[f][g][2], acc[f][g][3]);
        }
    }
}

// ---------------------------------------------------------------------------
// Kernel 4: assemble S from partials (sum K-splits, mirror)
// ---------------------------------------------------------------------------
__global__ void k_assemble() {
    int pid = blockIdx.x;
    int bi = (int)((sqrtf(8.f * (float)pid + 1.f) - 1.f) * 0.5f);
    while ((bi + 1) * (bi + 2) / 2 <= pid) bi++;
    while (bi * (bi + 1) / 2 > pid) bi--;
    int bj = pid - bi * (bi + 1) / 2;

    for (int e = threadIdx.x; e < TM * TN; e += blockDim.x) {
        float s = 0.f;
        #pragma unroll
        for (int ks = 0; ks < KSPLIT; ks++)
            s += g_P1[((size_t)ks * NPAIR + pid) * (size_t)(TM * TN) + e];
        int m = e >> 7, c = e & 127;
        int gi = bi * TM + m, gj = bj * TM + c;
        g_S[(size_t)gi * N + gj] = s;
        g_S[(size_t)gj * N + gi] = s;
    }
}

// ---------------------------------------------------------------------------
// Kernel 5: hard mining per row.
// dist[i,j] = 0.5 - S[i,j] / (2*(O[i,j]+1)),  O = popc(mask_i & mask_j)
// ---------------------------------------------------------------------------
__global__ void k_mine(const int* __restrict__ lbl) {
    int i = blockIdx.x;
    int stride = g_lbl_stride;
    int li = lbl[(size_t)i * stride];
    unsigned mi = g_mask[i];

    float ap = -1e30f, an = 1e30f;
    for (int j = threadIdx.x; j < N; j += blockDim.x) {
        float s = g_S[(size_t)i * N + j];
        float o = (float)__popc(mi & g_mask[j]);
        float dist = 0.5f - s / (2.f * (o + 1.f));
        if (lbl[(size_t)j * stride] == li) ap = fmaxf(ap, dist);
        else                               an = fminf(an, dist);
    }

    __shared__ float sap[256], san[256];
    sap[threadIdx.x] = ap;
    san[threadIdx.x] = an;
    __syncthreads();
    for (int o = 128; o; o >>= 1) {
        if (threadIdx.x < o) {
            sap[threadIdx.x] = fmaxf(sap[threadIdx.x], sap[threadIdx.x + o]);
            san[threadIdx.x] = fminf(san[threadIdx.x], san[threadIdx.x + o]);
        }
        __syncthreads();
    }
    if (threadIdx.x == 0)
        g_rowloss[i] = fmaxf(0.f, sap[0] - san[0] + MARGIN);
}

// ---------------------------------------------------------------------------
// Kernel 6: final mean
// ---------------------------------------------------------------------------
__global__ void k_final(float* __restrict__ out) {
    float s = 0.f;
    for (int j = threadIdx.x; j < N; j += blockDim.x)
        s += g_rowloss[j];
    __shared__ float red[8];
    #pragma unroll
    for (int o = 16; o; o >>= 1) s += __shfl_xor_sync(0xffffffffu, s, o);
    if ((threadIdx.x & 31) == 0) red[threadIdx.x >> 5] = s;
    __syncthreads();
    if (threadIdx.x == 0) {
        float t = 0.f;
        #pragma unroll
        for (int w = 0; w < 8; w++) t += red[w];
        out[0] = t / (float)N;
    }
}

// ---------------------------------------------------------------------------
extern "C" void kernel_launch(void* const* d_in, const int* in_sizes, int n_in,
                              void* d_out, int out_size) {
    const float* gf  = (const float*)d_in[0];   // global_feat  [N, D]
    const float* pf  = (const float*)d_in[1];   // partial_feat [N, P, D]
    const float* pl  = (const float*)d_in[2];   // part_labels  [N, P]
    const int*   lbl = (const int*)d_in[3];     // global_labels (int32 or int64)
    float* out = (float*)d_out;

    static int smem_set = 0;
    if (!smem_set) {
        cudaFuncSetAttribute(k_gemm_mma, cudaFuncAttributeMaxDynamicSharedMemorySize,
                             SMEM_TOTAL);
        smem_set = 1;
    }

    k_normalize<<<N * SEG, 256>>>(gf, pf, pl);
    k_meta<<<(N + 255) / 256, 256>>>(pl, lbl);
    k_gemm_mma<<<dim3(NPAIR, KSPLIT), 256, SMEM_TOTAL>>>();
    k_assemble<<<NPAIR, 256>>>();
    k_mine<<<N, 256>>>(lbl);
    k_final<<<1, 256>>>(out);
}

// round 9
// speedup vs baseline: 14.4835x; 1.2569x over previous
#include <cuda_runtime.h>
#include <cuda_fp16.h>
#include <math.h>
#include <stdint.h>

// Problem constants
#define N    1024
#define P    8
#define D    2048
#define SEG  9                 // 1 global + 8 parts
#define KTOT (SEG * D)         // 18432
#define MARGIN 0.3f

// GEMM tiling
#define TM   128
#define TN   128
#define TK   64                // K elements per smem chunk (128B fp16 rows)
#define NBLK (N / TM)          // 8
#define NPAIR (NBLK * (NBLK + 1) / 2)   // 36 triangle pairs
#define KSPLIT 8
#define KPER  (KTOT / KSPLIT)  // 2304
#define NCHUNK (KPER / TK)     // 36

// smem: per stage A tile (16KB) + B tile (16KB); 3 stages
#define TILE_B   (TM * TK * 2)         // 16384
#define STAGE_B  (2 * TILE_B)          // 32768
#define NSTAGE   3
#define SMEM_TOTAL (NSTAGE * STAGE_B)  // 98304

// Scratch (device globals: allocation-free rule)
__device__ __half    g_Hf[(size_t)N * KTOT];   // fp16 features
__device__ float     g_S[(size_t)N * N];       // gram matrix (atomic-accumulated)
__device__ float     g_rowloss[N];
__device__ unsigned  g_mask[N];
__device__ int       g_lbl_stride;   // 1 = int32 labels, 2 = int64 labels

// ---------------------------------------------------------------------------
// PTX helpers (sm_80-era: valid on plain compute_103 target)
// ---------------------------------------------------------------------------
__device__ __forceinline__ uint32_t smem_u32(const void* p) {
    uint32_t a;
    asm("{ .reg .u64 t; cvta.to.shared.u64 t, %1; cvt.u32.u64 %0, t; }" : "=r"(a) : "l"(p));
    return a;
}
#define LDSM_X4(r0, r1, r2, r3, addr) \
    asm volatile("ldmatrix.sync.aligned.m8n8.x4.shared.b16 {%0,%1,%2,%3}, [%4];" \
        : "=r"(r0), "=r"(r1), "=r"(r2), "=r"(r3) : "r"(addr))
#define MMA16816(d, a0, a1, a2, a3, b0, b1) \
    asm volatile("mma.sync.aligned.m16n8k16.row.col.f32.f16.f16.f32 " \
        "{%0,%1,%2,%3}, {%4,%5,%6,%7}, {%8,%9}, {%0,%1,%2,%3};" \
        : "+f"((d)[0]), "+f"((d)[1]), "+f"((d)[2]), "+f"((d)[3]) \
        : "r"(a0), "r"(a1), "r"(a2), "r"(a3), "r"(b0), "r"(b1))
#define CP_ASYNC16(dst, src) \
    asm volatile("cp.async.cg.shared.global [%0], [%1], 16;" :: "r"(dst), "l"(src))
#define CP_COMMIT() asm volatile("cp.async.commit_group;" ::: "memory")
#define CP_WAIT1()  asm volatile("cp.async.wait_group 1;" ::: "memory")

// ---------------------------------------------------------------------------
// Kernel 0: zero the gram matrix (atomic accumulation target)
// ---------------------------------------------------------------------------
__global__ void k_zero() {
    int i = blockIdx.x * blockDim.x + threadIdx.x;   // 1024*256 threads
    *(float4*)&g_S[(size_t)i * 4] = make_float4(0.f, 0.f, 0.f, 0.f);
}

// ---------------------------------------------------------------------------
// Kernel 1: single-pass normalize + fp16 pack (8 values/thread in regs)
// ---------------------------------------------------------------------------
__global__ void k_normalize(const float* __restrict__ gf,
                            const float* __restrict__ pf,
                            const float* __restrict__ pl) {
    int b = blockIdx.x;                  // 0 .. N*SEG-1
    int i = b / SEG;
    int s = b % SEG;
    const float* src = (s == 0) ? (gf + (size_t)i * D)
                                : (pf + ((size_t)i * P + (s - 1)) * D);

    float vals[8];
    float ss = 0.f;
    #pragma unroll
    for (int u = 0; u < 8; u++) {
        float v = src[threadIdx.x + 256 * u];
        vals[u] = v;
        ss += v * v;
    }
    __shared__ float red[8];
    #pragma unroll
    for (int o = 16; o; o >>= 1) ss += __shfl_xor_sync(0xffffffffu, ss, o);
    if ((threadIdx.x & 31) == 0) red[threadIdx.x >> 5] = ss;
    __syncthreads();
    if (threadIdx.x < 8) {
        float v = red[threadIdx.x];
        #pragma unroll
        for (int o = 4; o; o >>= 1) v += __shfl_xor_sync(0xffu, v, o);
        if (threadIdx.x == 0) red[0] = v;
    }
    __syncthreads();

    float scale = 1.f / (sqrtf(red[0]) + 1e-12f);
    if (s > 0) scale *= pl[(size_t)i * P + (s - 1)];

    __half* dst = g_Hf + (size_t)i * KTOT + (size_t)s * D;
    #pragma unroll
    for (int u = 0; u < 8; u++)
        dst[threadIdx.x + 256 * u] = __float2half(vals[u] * scale);
}

// ---------------------------------------------------------------------------
// Kernel 2: meta — part-label bitmasks + label dtype detect (fused)
// ---------------------------------------------------------------------------
__global__ void k_meta(const float* __restrict__ pl, const int* __restrict__ lbl) {
    int i = blockIdx.x * blockDim.x + threadIdx.x;
    if (i < N) {
        unsigned m = 0;
        #pragma unroll
        for (int k = 0; k < P; k++)
            if (pl[(size_t)i * P + k] != 0.f) m |= (1u << k);
        g_mask[i] = m;
    }
    if (blockIdx.x == 0) {
        __shared__ int any;
        if (threadIdx.x == 0) any = 0;
        __syncthreads();
        int v = 0;
        for (int j = 1 + 2 * threadIdx.x; j < N; j += 2 * blockDim.x)
            v |= lbl[j];
        if (v) atomicOr(&any, 1);
        __syncthreads();
        if (threadIdx.x == 0) g_lbl_stride = any ? 1 : 2;
    }
}

// ---------------------------------------------------------------------------
// Kernel 3: HMMA fp16 GEMM, triangle 128x128 tiles, K-split x8.
// 8 warps (2x4), warp tile 64x32, m16n8k16, 3-stage cp.async pipeline.
// Epilogue: atomicAdd (RED) straight into g_S — no partial buffer, no
// reduce kernel. Mirror writes skipped on diagonal blocks (would double-count).
// ---------------------------------------------------------------------------
__global__ void __launch_bounds__(256, 2) k_gemm_mma() {
    extern __shared__ char smem[];
    uint32_t sbase = smem_u32(smem);

    int tid  = threadIdx.x;
    int lane = tid & 31;
    int wid  = tid >> 5;
    int wm   = wid >> 2;      // 0..1  (M warp row)
    int wn   = wid & 3;       // 0..3  (N warp col)

    // triangle pair decode
    int pid = blockIdx.x;
    int bi = (int)((sqrtf(8.f * (float)pid + 1.f) - 1.f) * 0.5f);
    while ((bi + 1) * (bi + 2) / 2 <= pid) bi++;
    while (bi * (bi + 1) / 2 > pid) bi--;
    int bj = pid - bi * (bi + 1) / 2;     // bj <= bi
    int kbase = blockIdx.y * KPER;

    // cp.async source/dest mapping: per thread covers 4 rows (stride 32) of A
    // and 4 rows of B. r = tid>>3 (0..31), c16 = tid&7 (16B chunk).
    int rA  = tid >> 3;
    int c16 = tid & 7;
    const __half* srcA = g_Hf + (size_t)(bi * TM + rA) * KTOT + kbase + c16 * 8;
    const __half* srcB = g_Hf + (size_t)(bj * TM + rA) * KTOT + kbase + c16 * 8;
    // swizzled smem offset within tile; q-advance is +4096 (r+=32 keeps r&7)
    uint32_t pso = (uint32_t)(rA * 128 + ((c16 ^ (rA & 7)) << 4));

    // ldmatrix bases (within stage). Fragment row offsets are multiples of 8,
    // so the swizzle XOR operand is lane&7 for both A and B.
    uint32_t r7 = (uint32_t)(lane & 7);
    uint32_t aBase[4];
    #pragma unroll
    for (int f = 0; f < 4; f++)
        aBase[f] = sbase + (uint32_t)((wm * 64 + f * 16 + (lane & 15)) * 128);
    uint32_t aHalf = (uint32_t)(lane >> 4);
    uint32_t bBase[2];
    #pragma unroll
    for (int gp = 0; gp < 2; gp++)
        bBase[gp] = sbase + TILE_B +
            (uint32_t)((wn * 32 + gp * 16 + ((lane >> 4) << 3) + (lane & 7)) * 128);
    uint32_t bHalf = (uint32_t)((lane >> 3) & 1);

    float acc[4][4][4];
    #pragma unroll
    for (int i = 0; i < 4; i++)
        #pragma unroll
        for (int j = 0; j < 4; j++)
            #pragma unroll
            for (int e = 0; e < 4; e++) acc[i][j][e] = 0.f;

    // chunk issue: 4 A + 4 B cp.asyncs, stride KTOT*32 halfs in gmem, 4096B smem
    auto issue = [&](int t) {
        if (t < NCHUNK) {
            uint32_t st = (uint32_t)(t % NSTAGE) * STAGE_B;
            uint32_t dA = sbase + st + pso;
            uint32_t dB = dA + TILE_B;
            const __half* sA = srcA + (size_t)t * TK;
            const __half* sB = srcB + (size_t)t * TK;
            #pragma unroll
            for (int q = 0; q < 4; q++) {
                CP_ASYNC16(dA + q * 4096, sA + (size_t)q * 32 * KTOT);
                CP_ASYNC16(dB + q * 4096, sB + (size_t)q * 32 * KTOT);
            }
        }
        CP_COMMIT();
    };

    issue(0);
    issue(1);

    for (int t = 0; t < NCHUNK; t++) {
        CP_WAIT1();              // chunk t resident (<=1 group outstanding)
        __syncthreads();

        uint32_t boff = (uint32_t)(t % NSTAGE) * STAGE_B;
        #pragma unroll
        for (int s = 0; s < 4; s++) {              // 4 k16 steps per chunk
            uint32_t swA = ((2u * s + aHalf) ^ r7) << 4;
            uint32_t swB = ((2u * s + bHalf) ^ r7) << 4;
            uint32_t af[4][4];
            #pragma unroll
            for (int f = 0; f < 4; f++)
                LDSM_X4(af[f][0], af[f][1], af[f][2], af[f][3],
                        aBase[f] + boff + swA);
            uint32_t bf[4][2];
            #pragma unroll
            for (int gp = 0; gp < 2; gp++) {
                uint32_t r0, r1, r2, r3;
                LDSM_X4(r0, r1, r2, r3, bBase[gp] + boff + swB);
                bf[gp * 2][0] = r0;     bf[gp * 2][1] = r1;
                bf[gp * 2 + 1][0] = r2; bf[gp * 2 + 1][1] = r3;
            }
            #pragma unroll
            for (int f = 0; f < 4; f++)
                #pragma unroll
                for (int g = 0; g < 4; g++)
                    MMA16816(acc[f][g], af[f][0], af[f][1], af[f][2], af[f][3],
                             bf[g][0], bf[g][1]);
        }

        issue(t + 2);            // writes stage (t-1)%3, free since top sync
    }

    // epilogue: RED.ADD.F32 accumulate into g_S (direct + mirror).
    // c-frag mapping: rows lane>>2 (+8), cols 2*(lane&3).
    bool offdiag = (bi != bj);
    #pragma unroll
    for (int f = 0; f < 4; f++) {
        #pragma unroll
        for (int g = 0; g < 4; g++) {
            int row0 = bi * TM + wm * 64 + f * 16 + (lane >> 2);
            int col0 = bj * TM + wn * 32 + g * 8 + 2 * (lane & 3);
            atomicAdd(&g_S[(size_t)row0 * N + col0],       acc[f][g][0]);
            atomicAdd(&g_S[(size_t)row0 * N + col0 + 1],   acc[f][g][1]);
            atomicAdd(&g_S[(size_t)(row0 + 8) * N + col0],     acc[f][g][2]);
            atomicAdd(&g_S[(size_t)(row0 + 8) * N + col0 + 1], acc[f][g][3]);
            if (offdiag) {
                atomicAdd(&g_S[(size_t)col0 * N + row0],       acc[f][g][0]);
                atomicAdd(&g_S[(size_t)(col0 + 1) * N + row0], acc[f][g][1]);
                atomicAdd(&g_S[(size_t)col0 * N + row0 + 8],       acc[f][g][2]);
                atomicAdd(&g_S[(size_t)(col0 + 1) * N + row0 + 8], acc[f][g][3]);
            }
        }
    }
}

// ---------------------------------------------------------------------------
// Kernel 4: hard mining per row.
// dist[i,j] = 0.5 - S[i,j] / (2*(O[i,j]+1)),  O = popc(mask_i & mask_j)
// ---------------------------------------------------------------------------
__global__ void k_mine(const int* __restrict__ lbl) {
    int i = blockIdx.x;
    int stride = g_lbl_stride;
    int li = lbl[(size_t)i * stride];
    unsigned mi = g_mask[i];

    float ap = -1e30f, an = 1e30f;
    for (int j = threadIdx.x; j < N; j += blockDim.x) {
        float s = g_S[(size_t)i * N + j];
        float o = (float)__popc(mi & g_mask[j]);
        float dist = 0.5f - s / (2.f * (o + 1.f));
        if (lbl[(size_t)j * stride] == li) ap = fmaxf(ap, dist);
        else                               an = fminf(an, dist);
    }

    __shared__ float sap[256], san[256];
    sap[threadIdx.x] = ap;
    san[threadIdx.x] = an;
    __syncthreads();
    for (int o = 128; o; o >>= 1) {
        if (threadIdx.x < o) {
            sap[threadIdx.x] = fmaxf(sap[threadIdx.x], sap[threadIdx.x + o]);
            san[threadIdx.x] = fminf(san[threadIdx.x], san[threadIdx.x + o]);
        }
        __syncthreads();
    }
    if (threadIdx.x == 0)
        g_rowloss[i] = fmaxf(0.f, sap[0] - san[0] + MARGIN);
}

// ---------------------------------------------------------------------------
// Kernel 5: final mean
// ---------------------------------------------------------------------------
__global__ void k_final(float* __restrict__ out) {
    float s = 0.f;
    for (int j = threadIdx.x; j < N; j += blockDim.x)
        s += g_rowloss[j];
    __shared__ float red[8];
    #pragma unroll
    for (int o = 16; o; o >>= 1) s += __shfl_xor_sync(0xffffffffu, s, o);
    if ((threadIdx.x & 31) == 0) red[threadIdx.x >> 5] = s;
    __syncthreads();
    if (threadIdx.x == 0) {
        float t = 0.f;
        #pragma unroll
        for (int w = 0; w < 8; w++) t += red[w];
        out[0] = t / (float)N;
    }
}

// ---------------------------------------------------------------------------
extern "C" void kernel_launch(void* const* d_in, const int* in_sizes, int n_in,
                              void* d_out, int out_size) {
    const float* gf  = (const float*)d_in[0];   // global_feat  [N, D]
    const float* pf  = (const float*)d_in[1];   // partial_feat [N, P, D]
    const float* pl  = (const float*)d_in[2];   // part_labels  [N, P]
    const int*   lbl = (const int*)d_in[3];     // global_labels (int32 or int64)
    float* out = (float*)d_out;

    static int smem_set = 0;
    if (!smem_set) {
        cudaFuncSetAttribute(k_gemm_mma, cudaFuncAttributeMaxDynamicSharedMemorySize,
                             SMEM_TOTAL);
        smem_set = 1;
    }

    k_zero<<<N * N / (4 * 256), 256>>>();
    k_normalize<<<N * SEG, 256>>>(gf, pf, pl);
    k_meta<<<(N + 255) / 256, 256>>>(pl, lbl);
    k_gemm_mma<<<dim3(NPAIR, KSPLIT), 256, SMEM_TOTAL>>>();
    k_mine<<<N, 256>>>(lbl);
    k_final<<<1, 256>>>(out);
}

// round 10
// speedup vs baseline: 14.7188x; 1.0162x over previous
#include <cuda_runtime.h>
#include <cuda_fp16.h>
#include <math.h>
#include <stdint.h>

// Problem constants
#define N    1024
#define P    8
#define D    2048
#define SEG  9                 // 1 global + 8 parts
#define KTOT (SEG * D)         // 18432
#define MARGIN 0.3f

// GEMM tiling
#define TM   128
#define TN   128
#define TK   64                // K elements per smem chunk (128B fp16 rows)
#define NBLK (N / TM)          // 8
#define NPAIR (NBLK * (NBLK + 1) / 2)   // 36 triangle pairs
#define KSPLIT 8
#define KPER  (KTOT / KSPLIT)  // 2304
#define NCHUNK (KPER / TK)     // 36

// smem: per stage A tile (16KB) + B tile (16KB); 3 stages
#define TILE_B   (TM * TK * 2)         // 16384
#define STAGE_B  (2 * TILE_B)          // 32768
#define NSTAGE   3
#define SMEM_TOTAL (NSTAGE * STAGE_B)  // 98304

// Scratch (device globals: allocation-free rule)
__device__ __half    g_Hf[(size_t)N * KTOT];   // fp16 features
__device__ float     g_S[(size_t)N * N];       // gram matrix (atomic-accumulated)
__device__ float     g_rowloss[N];
__device__ unsigned  g_mask[N];
__device__ int       g_lbl_stride;   // 1 = int32 labels, 2 = int64 labels

// ---------------------------------------------------------------------------
// PTX helpers (sm_80-era: valid on plain compute_103 target)
// ---------------------------------------------------------------------------
__device__ __forceinline__ uint32_t smem_u32(const void* p) {
    uint32_t a;
    asm("{ .reg .u64 t; cvta.to.shared.u64 t, %1; cvt.u32.u64 %0, t; }" : "=r"(a) : "l"(p));
    return a;
}
#define LDSM_X4(r0, r1, r2, r3, addr) \
    asm volatile("ldmatrix.sync.aligned.m8n8.x4.shared.b16 {%0,%1,%2,%3}, [%4];" \
        : "=r"(r0), "=r"(r1), "=r"(r2), "=r"(r3) : "r"(addr))
#define MMA16816(d, a0, a1, a2, a3, b0, b1) \
    asm volatile("mma.sync.aligned.m16n8k16.row.col.f32.f16.f16.f32 " \
        "{%0,%1,%2,%3}, {%4,%5,%6,%7}, {%8,%9}, {%0,%1,%2,%3};" \
        : "+f"((d)[0]), "+f"((d)[1]), "+f"((d)[2]), "+f"((d)[3]) \
        : "r"(a0), "r"(a1), "r"(a2), "r"(a3), "r"(b0), "r"(b1))
#define CP_ASYNC16(dst, src) \
    asm volatile("cp.async.cg.shared.global [%0], [%1], 16;" :: "r"(dst), "l"(src))
#define CP_COMMIT() asm volatile("cp.async.commit_group;" ::: "memory")
#define CP_WAIT1()  asm volatile("cp.async.wait_group 1;" ::: "memory")

// ---------------------------------------------------------------------------
// Kernel 1: prep — normalize + fp16 pack, fused with g_S zeroing, part-mask
// packing, and label-dtype detect (saves two kernel launches).
// ---------------------------------------------------------------------------
__global__ void k_prep(const float* __restrict__ gf,
                       const float* __restrict__ pf,
                       const float* __restrict__ pl,
                       const int* __restrict__ lbl) {
    int b = blockIdx.x;                  // 0 .. N*SEG-1
    int i = b / SEG;
    int s = b % SEG;

    // fused: blocks 0..N-1 zero one row of g_S (must precede GEMM REDs;
    // guaranteed by stream ordering of kernel launches)
    if (b < N)
        *(float4*)&g_S[(size_t)b * N + (size_t)threadIdx.x * 4] =
            make_float4(0.f, 0.f, 0.f, 0.f);

    // fused: per-row part mask (one thread per seg-0 block)
    if (s == 0 && threadIdx.x == 0) {
        unsigned m = 0;
        #pragma unroll
        for (int k = 0; k < P; k++)
            if (pl[(size_t)i * P + k] != 0.f) m |= (1u << k);
        g_mask[i] = m;
    }
    // fused: label dtype detect (block 0, warp 0 only; no extra syncs)
    if (b == 0 && threadIdx.x < 32) {
        int v = 0;
        for (int j = 1 + 2 * threadIdx.x; j < N; j += 64)
            v |= lbl[j];
        #pragma unroll
        for (int o = 16; o; o >>= 1) v |= __shfl_xor_sync(0xffffffffu, v, o);
        if (threadIdx.x == 0) g_lbl_stride = v ? 1 : 2;
    }

    const float* src = (s == 0) ? (gf + (size_t)i * D)
                                : (pf + ((size_t)i * P + (s - 1)) * D);

    float vals[8];
    float ss = 0.f;
    #pragma unroll
    for (int u = 0; u < 8; u++) {
        float v = src[threadIdx.x + 256 * u];
        vals[u] = v;
        ss += v * v;
    }
    __shared__ float red[8];
    #pragma unroll
    for (int o = 16; o; o >>= 1) ss += __shfl_xor_sync(0xffffffffu, ss, o);
    if ((threadIdx.x & 31) == 0) red[threadIdx.x >> 5] = ss;
    __syncthreads();
    if (threadIdx.x < 8) {
        float v = red[threadIdx.x];
        #pragma unroll
        for (int o = 4; o; o >>= 1) v += __shfl_xor_sync(0xffu, v, o);
        if (threadIdx.x == 0) red[0] = v;
    }
    __syncthreads();

    float scale = 1.f / (sqrtf(red[0]) + 1e-12f);
    if (s > 0) scale *= pl[(size_t)i * P + (s - 1)];

    __half* dst = g_Hf + (size_t)i * KTOT + (size_t)s * D;
    #pragma unroll
    for (int u = 0; u < 8; u++)
        dst[threadIdx.x + 256 * u] = __float2half(vals[u] * scale);
}

// ---------------------------------------------------------------------------
// Kernel 2: HMMA fp16 GEMM, triangle 128x128 tiles, K-split x8.
// 8 warps (2x4), warp tile 64x32, m16n8k16, 3-stage cp.async pipeline,
// A-fragment double buffering so MMAs of step s overlap LDSM of step s+1.
// Epilogue: atomicAdd (RED) straight into g_S; mirror skipped on diagonal.
// ---------------------------------------------------------------------------
__global__ void __launch_bounds__(256, 2) k_gemm_mma() {
    extern __shared__ char smem[];
    uint32_t sbase = smem_u32(smem);

    int tid  = threadIdx.x;
    int lane = tid & 31;
    int wid  = tid >> 5;
    int wm   = wid >> 2;      // 0..1  (M warp row)
    int wn   = wid & 3;       // 0..3  (N warp col)

    // triangle pair decode
    int pid = blockIdx.x;
    int bi = (int)((sqrtf(8.f * (float)pid + 1.f) - 1.f) * 0.5f);
    while ((bi + 1) * (bi + 2) / 2 <= pid) bi++;
    while (bi * (bi + 1) / 2 > pid) bi--;
    int bj = pid - bi * (bi + 1) / 2;     // bj <= bi
    int kbase = blockIdx.y * KPER;

    // cp.async mapping: r = tid>>3 (0..31, +32 stride x4), c16 = tid&7
    int rA  = tid >> 3;
    int c16 = tid & 7;
    const __half* srcA = g_Hf + (size_t)(bi * TM + rA) * KTOT + kbase + c16 * 8;
    const __half* srcB = g_Hf + (size_t)(bj * TM + rA) * KTOT + kbase + c16 * 8;
    uint32_t pso = (uint32_t)(rA * 128 + ((c16 ^ (rA & 7)) << 4));

    // ldmatrix bases; fragment rows are multiples of 8 -> XOR operand lane&7
    uint32_t r7 = (uint32_t)(lane & 7);
    uint32_t aBase[4];
    #pragma unroll
    for (int f = 0; f < 4; f++)
        aBase[f] = sbase + (uint32_t)((wm * 64 + f * 16 + (lane & 15)) * 128);
    uint32_t aHalf = (uint32_t)(lane >> 4);
    uint32_t bBase[2];
    #pragma unroll
    for (int gp = 0; gp < 2; gp++)
        bBase[gp] = sbase + TILE_B +
            (uint32_t)((wn * 32 + gp * 16 + ((lane >> 4) << 3) + (lane & 7)) * 128);
    uint32_t bHalf = (uint32_t)((lane >> 3) & 1);

    float acc[4][4][4];
    #pragma unroll
    for (int i = 0; i < 4; i++)
        #pragma unroll
        for (int j = 0; j < 4; j++)
            #pragma unroll
            for (int e = 0; e < 4; e++) acc[i][j][e] = 0.f;

    auto issue = [&](int t) {
        if (t < NCHUNK) {
            uint32_t st = (uint32_t)(t % NSTAGE) * STAGE_B;
            uint32_t dA = sbase + st + pso;
            uint32_t dB = dA + TILE_B;
            const __half* sA = srcA + (size_t)t * TK;
            const __half* sB = srcB + (size_t)t * TK;
            #pragma unroll
            for (int q = 0; q < 4; q++) {
                CP_ASYNC16(dA + q * 4096, sA + (size_t)q * 32 * KTOT);
                CP_ASYNC16(dB + q * 4096, sB + (size_t)q * 32 * KTOT);
            }
        }
        CP_COMMIT();
    };

    issue(0);
    issue(1);

    for (int t = 0; t < NCHUNK; t++) {
        CP_WAIT1();              // chunk t resident (group t+1 may be in flight)
        __syncthreads();
        issue(t + 2);            // overwrites stage (t-1)%3: consumed pre-sync

        uint32_t boff = (uint32_t)(t % NSTAGE) * STAGE_B;

        uint32_t af[2][4][4];
        // preload A fragments for step 0
        {
            uint32_t swA0 = (aHalf ^ r7) << 4;
            #pragma unroll
            for (int f = 0; f < 4; f++)
                LDSM_X4(af[0][f][0], af[0][f][1], af[0][f][2], af[0][f][3],
                        aBase[f] + boff + swA0);
        }

        #pragma unroll
        for (int s = 0; s < 4; s++) {              // 4 k16 steps per chunk
            int cur = s & 1;
            // B fragments for this step
            uint32_t swB = ((2u * s + bHalf) ^ r7) << 4;
            uint32_t bf[4][2];
            #pragma unroll
            for (int gp = 0; gp < 2; gp++) {
                uint32_t r0, r1, r2, r3;
                LDSM_X4(r0, r1, r2, r3, bBase[gp] + boff + swB);
                bf[gp * 2][0] = r0;     bf[gp * 2][1] = r1;
                bf[gp * 2 + 1][0] = r2; bf[gp * 2 + 1][1] = r3;
            }
            // prefetch A fragments for next step (overlaps MMAs below)
            if (s < 3) {
                uint32_t swA = ((2u * (s + 1) + aHalf) ^ r7) << 4;
                #pragma unroll
                for (int f = 0; f < 4; f++)
                    LDSM_X4(af[cur ^ 1][f][0], af[cur ^ 1][f][1],
                            af[cur ^ 1][f][2], af[cur ^ 1][f][3],
                            aBase[f] + boff + swA);
            }
            #pragma unroll
            for (int f = 0; f < 4; f++)
                #pragma unroll
                for (int g = 0; g < 4; g++)
                    MMA16816(acc[f][g], af[cur][f][0], af[cur][f][1],
                             af[cur][f][2], af[cur][f][3],
                             bf[g][0], bf[g][1]);
        }
    }

    // epilogue: RED.ADD.F32 accumulate into g_S (direct + mirror).
    bool offdiag = (bi != bj);
    #pragma unroll
    for (int f = 0; f < 4; f++) {
        #pragma unroll
        for (int g = 0; g < 4; g++) {
            int row0 = bi * TM + wm * 64 + f * 16 + (lane >> 2);
            int col0 = bj * TM + wn * 32 + g * 8 + 2 * (lane & 3);
            atomicAdd(&g_S[(size_t)row0 * N + col0],       acc[f][g][0]);
            atomicAdd(&g_S[(size_t)row0 * N + col0 + 1],   acc[f][g][1]);
            atomicAdd(&g_S[(size_t)(row0 + 8) * N + col0],     acc[f][g][2]);
            atomicAdd(&g_S[(size_t)(row0 + 8) * N + col0 + 1], acc[f][g][3]);
            if (offdiag) {
                atomicAdd(&g_S[(size_t)col0 * N + row0],       acc[f][g][0]);
                atomicAdd(&g_S[(size_t)(col0 + 1) * N + row0], acc[f][g][1]);
                atomicAdd(&g_S[(size_t)col0 * N + row0 + 8],       acc[f][g][2]);
                atomicAdd(&g_S[(size_t)(col0 + 1) * N + row0 + 8], acc[f][g][3]);
            }
        }
    }
}

// ---------------------------------------------------------------------------
// Kernel 3: hard mining per row.
// dist[i,j] = 0.5 - S[i,j] / (2*(O[i,j]+1)),  O = popc(mask_i & mask_j)
// ---------------------------------------------------------------------------
__global__ void k_mine(const int* __restrict__ lbl) {
    int i = blockIdx.x;
    int stride = g_lbl_stride;
    int li = lbl[(size_t)i * stride];
    unsigned mi = g_mask[i];

    float ap = -1e30f, an = 1e30f;
    for (int j = threadIdx.x; j < N; j += blockDim.x) {
        float s = g_S[(size_t)i * N + j];
        float o = (float)__popc(mi & g_mask[j]);
        float dist = 0.5f - s / (2.f * (o + 1.f));
        if (lbl[(size_t)j * stride] == li) ap = fmaxf(ap, dist);
        else                               an = fminf(an, dist);
    }

    __shared__ float sap[256], san[256];
    sap[threadIdx.x] = ap;
    san[threadIdx.x] = an;
    __syncthreads();
    for (int o = 128; o; o >>= 1) {
        if (threadIdx.x < o) {
            sap[threadIdx.x] = fmaxf(sap[threadIdx.x], sap[threadIdx.x + o]);
            san[threadIdx.x] = fminf(san[threadIdx.x], san[threadIdx.x + o]);
        }
        __syncthreads();
    }
    if (threadIdx.x == 0)
        g_rowloss[i] = fmaxf(0.f, sap[0] - san[0] + MARGIN);
}

// ---------------------------------------------------------------------------
// Kernel 4: final mean
// ---------------------------------------------------------------------------
__global__ void k_final(float* __restrict__ out) {
    float s = 0.f;
    for (int j = threadIdx.x; j < N; j += blockDim.x)
        s += g_rowloss[j];
    __shared__ float red[8];
    #pragma unroll
    for (int o = 16; o; o >>= 1) s += __shfl_xor_sync(0xffffffffu, s, o);
    if ((threadIdx.x & 31) == 0) red[threadIdx.x >> 5] = s;
    __syncthreads();
    if (threadIdx.x == 0) {
        float t = 0.f;
        #pragma unroll
        for (int w = 0; w < 8; w++) t += red[w];
        out[0] = t / (float)N;
    }
}

// ---------------------------------------------------------------------------
extern "C" void kernel_launch(void* const* d_in, const int* in_sizes, int n_in,
                              void* d_out, int out_size) {
    const float* gf  = (const float*)d_in[0];   // global_feat  [N, D]
    const float* pf  = (const float*)d_in[1];   // partial_feat [N, P, D]
    const float* pl  = (const float*)d_in[2];   // part_labels  [N, P]
    const int*   lbl = (const int*)d_in[3];     // global_labels (int32 or int64)
    float* out = (float*)d_out;

    static int smem_set = 0;
    if (!smem_set) {
        cudaFuncSetAttribute(k_gemm_mma, cudaFuncAttributeMaxDynamicSharedMemorySize,
                             SMEM_TOTAL);
        smem_set = 1;
    }

    k_prep<<<N * SEG, 256>>>(gf, pf, pl, lbl);
    k_gemm_mma<<<dim3(NPAIR, KSPLIT), 256, SMEM_TOTAL>>>();
    k_mine<<<N, 256>>>(lbl);
    k_final<<<1, 256>>>(out);
}

// round 11
// speedup vs baseline: 15.8981x; 1.0801x over previous
#include <cuda_runtime.h>
#include <cuda_fp16.h>
#include <math.h>
#include <stdint.h>

// Problem constants
#define N    1024
#define P    8
#define D    2048
#define SEG  9                 // 1 global + 8 parts
#define MARGIN 0.3f

// GEMM tiling (per segment: K = D = 2048)
#define TM   128
#define TN   128
#define TK   64                // K elements per smem chunk (128B fp16 rows)
#define NTILE (N / TM)         // 8 tiles max per segment
#define NPAIR (NTILE * (NTILE + 1) / 2)   // 36 triangle pairs
#define KSPLIT 4
#define KPER  (D / KSPLIT)     // 512
#define NCHUNK (KPER / TK)     // 8

// smem: per stage A tile (16KB) + B tile (16KB); 3 stages
#define TILE_B   (TM * TK * 2)         // 16384
#define STAGE_B  (2 * TILE_B)          // 32768
#define NSTAGE   3
#define SMEM_TOTAL (NSTAGE * STAGE_B)  // 98304

// Scratch (device globals: allocation-free rule)
__device__ __half    g_Hf[(size_t)SEG * N * D];  // per-segment fp16 features
__device__ float     g_S[(size_t)N * N];         // gram (atomic-accumulated)
__device__ unsigned  g_mask[N];
__device__ int       g_idx[SEG][N];              // compacted row ids (parts)
__device__ int       g_cnt[SEG];
__device__ int       g_lbl_stride;   // 1 = int32 labels, 2 = int64 labels

// ---------------------------------------------------------------------------
// PTX helpers (sm_80-era: valid on plain compute_103 target)
// ---------------------------------------------------------------------------
__device__ __forceinline__ uint32_t smem_u32(const void* p) {
    uint32_t a;
    asm("{ .reg .u64 t; cvta.to.shared.u64 t, %1; cvt.u32.u64 %0, t; }" : "=r"(a) : "l"(p));
    return a;
}
#define LDSM_X4(r0, r1, r2, r3, addr) \
    asm volatile("ldmatrix.sync.aligned.m8n8.x4.shared.b16 {%0,%1,%2,%3}, [%4];" \
        : "=r"(r0), "=r"(r1), "=r"(r2), "=r"(r3) : "r"(addr))
#define MMA16816(d, a0, a1, a2, a3, b0, b1) \
    asm volatile("mma.sync.aligned.m16n8k16.row.col.f32.f16.f16.f32 " \
        "{%0,%1,%2,%3}, {%4,%5,%6,%7}, {%8,%9}, {%0,%1,%2,%3};" \
        : "+f"((d)[0]), "+f"((d)[1]), "+f"((d)[2]), "+f"((d)[3]) \
        : "r"(a0), "r"(a1), "r"(a2), "r"(a3), "r"(b0), "r"(b1))
#define CP_ASYNC16(dst, src) \
    asm volatile("cp.async.cg.shared.global [%0], [%1], 16;" :: "r"(dst), "l"(src))
#define CP_COMMIT() asm volatile("cp.async.commit_group;" ::: "memory")
#define CP_WAIT1()  asm volatile("cp.async.wait_group 1;" ::: "memory")

// ---------------------------------------------------------------------------
// Kernel 1: prep — normalize + fp16 pack into per-segment layout, fused with
// g_S zeroing, out zeroing, part-mask packing, label-dtype detect.
// Part segments with label==0 are skipped entirely (never read by the GEMM).
// ---------------------------------------------------------------------------
__global__ void k_prep(const float* __restrict__ gf,
                       const float* __restrict__ pf,
                       const float* __restrict__ pl,
                       const int* __restrict__ lbl,
                       float* __restrict__ out) {
    int b = blockIdx.x;                  // 0 .. N*SEG-1
    int i = b / SEG;
    int s = b % SEG;

    // fused: blocks 0..N-1 zero one row of g_S
    if (b < N)
        *(float4*)&g_S[(size_t)b * N + (size_t)threadIdx.x * 4] =
            make_float4(0.f, 0.f, 0.f, 0.f);

    if (s == 0 && threadIdx.x == 0) {
        unsigned m = 0;
        #pragma unroll
        for (int k = 0; k < P; k++)
            if (pl[(size_t)i * P + k] != 0.f) m |= (1u << k);
        g_mask[i] = m;
        if (b == 0) out[0] = 0.f;        // k_mine atomically accumulates mean
    }
    if (b == 0 && threadIdx.x >= 32 && threadIdx.x < 64) {
        int lane = threadIdx.x - 32;
        int v = 0;
        for (int j = 1 + 2 * lane; j < N; j += 64) v |= lbl[j];
        #pragma unroll
        for (int o = 16; o; o >>= 1) v |= __shfl_xor_sync(0xffffffffu, v, o);
        if (lane == 0) g_lbl_stride = v ? 1 : 2;
    }

    float plv = 1.f;
    if (s > 0) {
        plv = pl[(size_t)i * P + (s - 1)];
        if (plv == 0.f) return;          // zero segment: never read downstream
    }
    const float* src = (s == 0) ? (gf + (size_t)i * D)
                                : (pf + ((size_t)i * P + (s - 1)) * D);

    float vals[8];
    float ss = 0.f;
    #pragma unroll
    for (int u = 0; u < 8; u++) {
        float v = src[threadIdx.x + 256 * u];
        vals[u] = v;
        ss += v * v;
    }
    __shared__ float red[8];
    #pragma unroll
    for (int o = 16; o; o >>= 1) ss += __shfl_xor_sync(0xffffffffu, ss, o);
    if ((threadIdx.x & 31) == 0) red[threadIdx.x >> 5] = ss;
    __syncthreads();
    if (threadIdx.x < 8) {
        float v = red[threadIdx.x];
        #pragma unroll
        for (int o = 4; o; o >>= 1) v += __shfl_xor_sync(0xffu, v, o);
        if (threadIdx.x == 0) red[0] = v;
    }
    __syncthreads();

    float scale = plv / (sqrtf(red[0]) + 1e-12f);
    __half* dst = g_Hf + ((size_t)s * N + i) * D;
    #pragma unroll
    for (int u = 0; u < 8; u++)
        dst[threadIdx.x + 256 * u] = __float2half(vals[u] * scale);
}

// ---------------------------------------------------------------------------
// Kernel 2: build compacted row-index lists per part (warp w -> part w)
// ---------------------------------------------------------------------------
__global__ void k_index() {
    int lane = threadIdx.x & 31;
    int w    = threadIdx.x >> 5;         // part 0..7 -> segment w+1
    unsigned total = 0;
    for (int c = 0; c < N / 32; c++) {
        int row = c * 32 + lane;
        int bit = (g_mask[row] >> w) & 1;
        unsigned bal = __ballot_sync(0xffffffffu, bit);
        if (bit)
            g_idx[w + 1][total + __popc(bal & ((1u << lane) - 1u))] = row;
        total += __popc(bal);
    }
    if (lane == 0) g_cnt[w + 1] = (int)total;
}

// ---------------------------------------------------------------------------
// Kernel 3: HMMA fp16 GEMM over compacted per-segment row sets.
// grid.x = seg*NPAIR + trianglePair, grid.y = K split.
// Row gather via index array at cp.async; scatter via atomicAdd epilogue.
// ---------------------------------------------------------------------------
__global__ void __launch_bounds__(256, 2) k_gemm_mma() {
    extern __shared__ char smem[];
    uint32_t sbase = smem_u32(smem);

    int tid  = threadIdx.x;
    int lane = tid & 31;
    int wid  = tid >> 5;
    int wm   = wid >> 2;      // 0..1  (M warp row)
    int wn   = wid & 3;       // 0..3  (N warp col)

    int seg = blockIdx.x / NPAIR;
    int pid = blockIdx.x % NPAIR;
    int ti = (int)((sqrtf(8.f * (float)pid + 1.f) - 1.f) * 0.5f);
    while ((ti + 1) * (ti + 2) / 2 <= pid) ti++;
    while (ti * (ti + 1) / 2 > pid) ti--;
    int tj = pid - ti * (ti + 1) / 2;     // tj <= ti

    int cnt = (seg == 0) ? N : g_cnt[seg];
    if (ti >= ((cnt + TM - 1) >> 7)) return;   // tile beyond row count

    int kbase = blockIdx.y * KPER;
    const __half* segbase = g_Hf + (size_t)seg * N * D;

    // gather offsets (elements) for cp.async: 4 rows each for A and B
    int rA  = tid >> 3;        // 0..31 (+32 per q)
    int c16 = tid & 7;
    uint32_t offA[4], offB[4];
    #pragma unroll
    for (int q = 0; q < 4; q++) {
        int ga = ti * TM + rA + 32 * q;
        int gb = tj * TM + rA + 32 * q;
        int ia = (seg == 0) ? ga : g_idx[seg][min(ga, cnt - 1)];
        int ib = (seg == 0) ? gb : g_idx[seg][min(gb, cnt - 1)];
        offA[q] = (uint32_t)(ia * D + c16 * 8);
        offB[q] = (uint32_t)(ib * D + c16 * 8);
    }
    uint32_t pso = (uint32_t)(rA * 128 + ((c16 ^ (rA & 7)) << 4));

    // ldmatrix bases; fragment rows are multiples of 8 -> XOR operand lane&7
    uint32_t r7 = (uint32_t)(lane & 7);
    uint32_t aBase[4];
    #pragma unroll
    for (int f = 0; f < 4; f++)
        aBase[f] = sbase + (uint32_t)((wm * 64 + f * 16 + (lane & 15)) * 128);
    uint32_t aHalf = (uint32_t)(lane >> 4);
    uint32_t bBase[2];
    #pragma unroll
    for (int gp = 0; gp < 2; gp++)
        bBase[gp] = sbase + TILE_B +
            (uint32_t)((wn * 32 + gp * 16 + ((lane >> 4) << 3) + (lane & 7)) * 128);
    uint32_t bHalf = (uint32_t)((lane >> 3) & 1);

    float acc[4][4][4];
    #pragma unroll
    for (int i = 0; i < 4; i++)
        #pragma unroll
        for (int j = 0; j < 4; j++)
            #pragma unroll
            for (int e = 0; e < 4; e++) acc[i][j][e] = 0.f;

    auto issue = [&](int t) {
        if (t < NCHUNK) {
            uint32_t st = (uint32_t)(t % NSTAGE) * STAGE_B;
            uint32_t dA = sbase + st + pso;
            uint32_t dB = dA + TILE_B;
            const __half* sk = segbase + kbase + t * TK;
            #pragma unroll
            for (int q = 0; q < 4; q++) {
                CP_ASYNC16(dA + q * 4096, sk + offA[q]);
                CP_ASYNC16(dB + q * 4096, sk + offB[q]);
            }
        }
        CP_COMMIT();
    };

    issue(0);
    issue(1);

    for (int t = 0; t < NCHUNK; t++) {
        CP_WAIT1();
        __syncthreads();
        issue(t + 2);            // overwrites stage (t-1)%3: consumed pre-sync

        uint32_t boff = (uint32_t)(t % NSTAGE) * STAGE_B;
        #pragma unroll
        for (int s = 0; s < 4; s++) {              // 4 k16 steps per chunk
            uint32_t swA = ((2u * s + aHalf) ^ r7) << 4;
            uint32_t swB = ((2u * s + bHalf) ^ r7) << 4;
            uint32_t af[4][4];
            #pragma unroll
            for (int f = 0; f < 4; f++)
                LDSM_X4(af[f][0], af[f][1], af[f][2], af[f][3],
                        aBase[f] + boff + swA);
            uint32_t bf[4][2];
            #pragma unroll
            for (int gp = 0; gp < 2; gp++) {
                uint32_t r0, r1, r2, r3;
                LDSM_X4(r0, r1, r2, r3, bBase[gp] + boff + swB);
                bf[gp * 2][0] = r0;     bf[gp * 2][1] = r1;
                bf[gp * 2 + 1][0] = r2; bf[gp * 2 + 1][1] = r3;
            }
            #pragma unroll
            for (int f = 0; f < 4; f++)
                #pragma unroll
                for (int g = 0; g < 4; g++)
                    MMA16816(acc[f][g], af[f][0], af[f][1], af[f][2], af[f][3],
                             bf[g][0], bf[g][1]);
        }
    }

    // epilogue: scatter-accumulate into g_S with index remap + bounds check
    bool offdiag = (ti != tj);
    #pragma unroll
    for (int f = 0; f < 4; f++) {
        int rloc0 = ti * TM + wm * 64 + f * 16 + (lane >> 2);
        #pragma unroll
        for (int g = 0; g < 4; g++) {
            int cloc0 = tj * TM + wn * 32 + g * 8 + 2 * (lane & 3);
            #pragma unroll
            for (int a = 0; a < 2; a++) {
                int rl = rloc0 + a * 8;
                if (rl >= cnt) continue;
                int gi = (seg == 0) ? rl : g_idx[seg][rl];
                #pragma unroll
                for (int b2 = 0; b2 < 2; b2++) {
                    int cl = cloc0 + b2;
                    if (cl >= cnt) continue;
                    int gj = (seg == 0) ? cl : g_idx[seg][cl];
                    float v = acc[f][g][a * 2 + b2];
                    atomicAdd(&g_S[(size_t)gi * N + gj], v);
                    if (offdiag) atomicAdd(&g_S[(size_t)gj * N + gi], v);
                }
            }
        }
    }
}

// ---------------------------------------------------------------------------
// Kernel 4: hard mining per row + fused mean accumulation into out.
// dist[i,j] = 0.5 - S[i,j] / (2*(O[i,j]+1)),  O = popc(mask_i & mask_j)
// ---------------------------------------------------------------------------
__global__ void k_mine(const int* __restrict__ lbl, float* __restrict__ out) {
    int i = blockIdx.x;
    int stride = g_lbl_stride;
    int li = lbl[(size_t)i * stride];
    unsigned mi = g_mask[i];

    float ap = -1e30f, an = 1e30f;
    for (int j = threadIdx.x; j < N; j += blockDim.x) {
        float s = g_S[(size_t)i * N + j];
        float o = (float)__popc(mi & g_mask[j]);
        float dist = 0.5f - s / (2.f * (o + 1.f));
        if (lbl[(size_t)j * stride] == li) ap = fmaxf(ap, dist);
        else                               an = fminf(an, dist);
    }

    __shared__ float sap[256], san[256];
    sap[threadIdx.x] = ap;
    san[threadIdx.x] = an;
    __syncthreads();
    for (int o = 128; o; o >>= 1) {
        if (threadIdx.x < o) {
            sap[threadIdx.x] = fmaxf(sap[threadIdx.x], sap[threadIdx.x + o]);
            san[threadIdx.x] = fminf(san[threadIdx.x], san[threadIdx.x + o]);
        }
        __syncthreads();
    }
    if (threadIdx.x == 0)
        atomicAdd(out, fmaxf(0.f, sap[0] - san[0] + MARGIN) * (1.f / N));
}

// ---------------------------------------------------------------------------
extern "C" void kernel_launch(void* const* d_in, const int* in_sizes, int n_in,
                              void* d_out, int out_size) {
    const float* gf  = (const float*)d_in[0];   // global_feat  [N, D]
    const float* pf  = (const float*)d_in[1];   // partial_feat [N, P, D]
    const float* pl  = (const float*)d_in[2];   // part_labels  [N, P]
    const int*   lbl = (const int*)d_in[3];     // global_labels (int32 or int64)
    float* out = (float*)d_out;

    static int smem_set = 0;
    if (!smem_set) {
        cudaFuncSetAttribute(k_gemm_mma, cudaFuncAttributeMaxDynamicSharedMemorySize,
                             SMEM_TOTAL);
        smem_set = 1;
    }

    k_prep<<<N * SEG, 256>>>(gf, pf, pl, lbl, out);
    k_index<<<1, 256>>>();
    k_gemm_mma<<<dim3(SEG * NPAIR, KSPLIT), 256, SMEM_TOTAL>>>();
    k_mine<<<N, 256>>>(lbl, out);
}

// round 15
// speedup vs baseline: 19.8802x; 1.2505x over previous
#include <cuda_runtime.h>
#include <cuda_fp16.h>
#include <math.h>
#include <stdint.h>

// Problem constants
#define N    1024
#define P    8
#define D    2048
#define SEG  9                 // 1 global + 8 parts
#define MARGIN 0.3f

// GEMM tiling (per segment: K = D = 2048)
#define TM   128
#define TN   128
#define TK   64                // K elements per smem chunk (128B fp16 rows)
#define NTILE (N / TM)         // 8 tiles max per segment
#define NPAIR (NTILE * (NTILE + 1) / 2)   // 36 triangle pairs
#define KSPLIT 2
#define KPER  (D / KSPLIT)     // 1024
#define NCHUNK (KPER / TK)     // 16

// smem: per stage A tile (16KB) + B tile (16KB); 3 stages
#define TILE_B   (TM * TK * 2)         // 16384
#define STAGE_B  (2 * TILE_B)          // 32768
#define NSTAGE   3
#define SMEM_TOTAL (NSTAGE * STAGE_B)  // 98304

// Scratch (device globals: allocation-free rule)
__device__ __half    g_Hf[(size_t)SEG * N * D];  // per-segment fp16 features
__device__ float     g_S[(size_t)N * N];         // gram (lower tri atomic, mirrored)
__device__ unsigned  g_mask[N];
__device__ int       g_idx[SEG][N];              // compacted row ids (parts)
__device__ int       g_cnt[SEG];
__device__ int       g_lbl_stride;   // 1 = int32 labels, 2 = int64 labels

// ---------------------------------------------------------------------------
// PTX helpers (sm_80-era: valid on plain compute_103 target)
// ---------------------------------------------------------------------------
__device__ __forceinline__ uint32_t smem_u32(const void* p) {
    uint32_t a;
    asm("{ .reg .u64 t; cvta.to.shared.u64 t, %1; cvt.u32.u64 %0, t; }" : "=r"(a) : "l"(p));
    return a;
}
#define LDSM_X4(r0, r1, r2, r3, addr) \
    asm volatile("ldmatrix.sync.aligned.m8n8.x4.shared.b16 {%0,%1,%2,%3}, [%4];" \
        : "=r"(r0), "=r"(r1), "=r"(r2), "=r"(r3) : "r"(addr))
#define MMA16816(d, a0, a1, a2, a3, b0, b1) \
    asm volatile("mma.sync.aligned.m16n8k16.row.col.f32.f16.f16.f32 " \
        "{%0,%1,%2,%3}, {%4,%5,%6,%7}, {%8,%9}, {%0,%1,%2,%3};" \
        : "+f"((d)[0]), "+f"((d)[1]), "+f"((d)[2]), "+f"((d)[3]) \
        : "r"(a0), "r"(a1), "r"(a2), "r"(a3), "r"(b0), "r"(b1))
#define CP_ASYNC16(dst, src) \
    asm volatile("cp.async.cg.shared.global [%0], [%1], 16;" :: "r"(dst), "l"(src))
#define CP_COMMIT() asm volatile("cp.async.commit_group;" ::: "memory")
#define CP_WAIT1()  asm volatile("cp.async.wait_group 1;" ::: "memory")

// ---------------------------------------------------------------------------
// Kernel 1: prep — normalize + fp16 pack (float2 in, half2 out), fused with
// g_S zeroing, out zeroing, part-mask packing, label-dtype detect.
// Part segments with label==0 are skipped entirely (never read by the GEMM).
// ---------------------------------------------------------------------------
__global__ void k_prep(const float* __restrict__ gf,
                       const float* __restrict__ pf,
                       const float* __restrict__ pl,
                       const int* __restrict__ lbl,
                       float* __restrict__ out) {
    int b = blockIdx.x;                  // 0 .. N*SEG-1
    int i = b / SEG;
    int s = b % SEG;

    // fused: blocks 0..N-1 zero one row of g_S
    if (b < N)
        *(float4*)&g_S[(size_t)b * N + (size_t)threadIdx.x * 4] =
            make_float4(0.f, 0.f, 0.f, 0.f);

    if (s == 0 && threadIdx.x == 0) {
        unsigned m = 0;
        #pragma unroll
        for (int k = 0; k < P; k++)
            if (pl[(size_t)i * P + k] != 0.f) m |= (1u << k);
        g_mask[i] = m;
        if (b == 0) out[0] = 0.f;        // k_mine atomically accumulates mean
    }
    if (b == 0 && threadIdx.x >= 32 && threadIdx.x < 64) {
        int lane = threadIdx.x - 32;
        int v = 0;
        for (int j = 1 + 2 * lane; j < N; j += 64) v |= lbl[j];
        #pragma unroll
        for (int o = 16; o; o >>= 1) v |= __shfl_xor_sync(0xffffffffu, v, o);
        if (lane == 0) g_lbl_stride = v ? 1 : 2;
    }

    float plv = 1.f;
    if (s > 0) {
        plv = pl[(size_t)i * P + (s - 1)];
        if (plv == 0.f) return;          // zero segment: never read downstream
    }
    const float2* src = (const float2*)((s == 0) ? (gf + (size_t)i * D)
                                : (pf + ((size_t)i * P + (s - 1)) * D));

    float2 vals[4];
    float ss = 0.f;
    #pragma unroll
    for (int u = 0; u < 4; u++) {
        float2 v = src[threadIdx.x + 256 * u];
        vals[u] = v;
        ss += v.x * v.x + v.y * v.y;
    }
    __shared__ float red[8];
    #pragma unroll
    for (int o = 16; o; o >>= 1) ss += __shfl_xor_sync(0xffffffffu, ss, o);
    if ((threadIdx.x & 31) == 0) red[threadIdx.x >> 5] = ss;
    __syncthreads();
    if (threadIdx.x < 8) {
        float v = red[threadIdx.x];
        #pragma unroll
        for (int o = 4; o; o >>= 1) v += __shfl_xor_sync(0xffu, v, o);
        if (threadIdx.x == 0) red[0] = v;
    }
    __syncthreads();

    float scale = plv / (sqrtf(red[0]) + 1e-12f);
    __half2* dst = (__half2*)(g_Hf + ((size_t)s * N + i) * D);
    #pragma unroll
    for (int u = 0; u < 4; u++)
        dst[threadIdx.x + 256 * u] =
            __floats2half2_rn(vals[u].x * scale, vals[u].y * scale);
}

// ---------------------------------------------------------------------------
// Kernel 2: build compacted row-index lists per part (warp w -> part w)
// ---------------------------------------------------------------------------
__global__ void k_index() {
    int lane = threadIdx.x & 31;
    int w    = threadIdx.x >> 5;         // part 0..7 -> segment w+1
    unsigned total = 0;
    for (int c = 0; c < N / 32; c++) {
        int row = c * 32 + lane;
        int bit = (g_mask[row] >> w) & 1;
        unsigned bal = __ballot_sync(0xffffffffu, bit);
        if (bit)
            g_idx[w + 1][total + __popc(bal & ((1u << lane) - 1u))] = row;
        total += __popc(bal);
    }
    if (lane == 0) g_cnt[w + 1] = (int)total;
}

// ---------------------------------------------------------------------------
// Kernel 3: HMMA fp16 GEMM over compacted per-segment row sets.
// grid.x = seg*NPAIR + trianglePair, grid.y = K split (2).
// Epilogue: atomicAdd of LOWER-triangle elements only (rank_row >= rank_col;
// sorted indices make rank order == row order). Upper filled by k_mirror.
// ---------------------------------------------------------------------------
__global__ void __launch_bounds__(256, 2) k_gemm_mma() {
    extern __shared__ char smem[];
    uint32_t sbase = smem_u32(smem);

    int tid  = threadIdx.x;
    int lane = tid & 31;
    int wid  = tid >> 5;
    int wm   = wid >> 2;      // 0..1  (M warp row)
    int wn   = wid & 3;       // 0..3  (N warp col)

    int seg = blockIdx.x / NPAIR;
    int pid = blockIdx.x % NPAIR;
    int ti = (int)((sqrtf(8.f * (float)pid + 1.f) - 1.f) * 0.5f);
    while ((ti + 1) * (ti + 2) / 2 <= pid) ti++;
    while (ti * (ti + 1) / 2 > pid) ti--;
    int tj = pid - ti * (ti + 1) / 2;     // tj <= ti

    int cnt = (seg == 0) ? N : g_cnt[seg];
    if (ti >= ((cnt + TM - 1) >> 7)) return;   // tile beyond row count

    int kbase = blockIdx.y * KPER;
    const __half* segbase = g_Hf + (size_t)seg * N * D;

    // gather offsets (elements) for cp.async: 4 rows each for A and B
    int rA  = tid >> 3;        // 0..31 (+32 per q)
    int c16 = tid & 7;
    uint32_t offA[4], offB[4];
    #pragma unroll
    for (int q = 0; q < 4; q++) {
        int ga = ti * TM + rA + 32 * q;
        int gb = tj * TM + rA + 32 * q;
        int ia = (seg == 0) ? ga : g_idx[seg][min(ga, cnt - 1)];
        int ib = (seg == 0) ? gb : g_idx[seg][min(gb, cnt - 1)];
        offA[q] = (uint32_t)(ia * D + c16 * 8);
        offB[q] = (uint32_t)(ib * D + c16 * 8);
    }
    uint32_t pso = (uint32_t)(rA * 128 + ((c16 ^ (rA & 7)) << 4));

    // ldmatrix bases; fragment rows are multiples of 8 -> XOR operand lane&7
    uint32_t r7 = (uint32_t)(lane & 7);
    uint32_t aBase[4];
    #pragma unroll
    for (int f = 0; f < 4; f++)
        aBase[f] = sbase + (uint32_t)((wm * 64 + f * 16 + (lane & 15)) * 128);
    uint32_t aHalf = (uint32_t)(lane >> 4);
    uint32_t bBase[2];
    #pragma unroll
    for (int gp = 0; gp < 2; gp++)
        bBase[gp] = sbase + TILE_B +
            (uint32_t)((wn * 32 + gp * 16 + ((lane >> 4) << 3) + (lane & 7)) * 128);
    uint32_t bHalf = (uint32_t)((lane >> 3) & 1);

    float acc[4][4][4];
    #pragma unroll
    for (int i = 0; i < 4; i++)
        #pragma unroll
        for (int j = 0; j < 4; j++)
            #pragma unroll
            for (int e = 0; e < 4; e++) acc[i][j][e] = 0.f;

    auto issue = [&](int t) {
        if (t < NCHUNK) {
            uint32_t st = (uint32_t)(t % NSTAGE) * STAGE_B;
            uint32_t dA = sbase + st + pso;
            uint32_t dB = dA + TILE_B;
            const __half* sk = segbase + kbase + t * TK;
            #pragma unroll
            for (int q = 0; q < 4; q++) {
                CP_ASYNC16(dA + q * 4096, sk + offA[q]);
                CP_ASYNC16(dB + q * 4096, sk + offB[q]);
            }
        }
        CP_COMMIT();
    };

    issue(0);
    issue(1);

    for (int t = 0; t < NCHUNK; t++) {
        CP_WAIT1();
        __syncthreads();
        issue(t + 2);            // overwrites stage (t-1)%3: consumed pre-sync

        uint32_t boff = (uint32_t)(t % NSTAGE) * STAGE_B;
        #pragma unroll
        for (int s = 0; s < 4; s++) {              // 4 k16 steps per chunk
            uint32_t swA = ((2u * s + aHalf) ^ r7) << 4;
            uint32_t swB = ((2u * s + bHalf) ^ r7) << 4;
            uint32_t af[4][4];
            #pragma unroll
            for (int f = 0; f < 4; f++)
                LDSM_X4(af[f][0], af[f][1], af[f][2], af[f][3],
                        aBase[f] + boff + swA);
            uint32_t bf[4][2];
            #pragma unroll
            for (int gp = 0; gp < 2; gp++) {
                uint32_t r0, r1, r2, r3;
                LDSM_X4(r0, r1, r2, r3, bBase[gp] + boff + swB);
                bf[gp * 2][0] = r0;     bf[gp * 2][1] = r1;
                bf[gp * 2 + 1][0] = r2; bf[gp * 2 + 1][1] = r3;
            }
            #pragma unroll
            for (int f = 0; f < 4; f++)
                #pragma unroll
                for (int g = 0; g < 4; g++)
                    MMA16816(acc[f][g], af[f][0], af[f][1], af[f][2], af[f][3],
                             bf[g][0], bf[g][1]);
        }
    }

    // epilogue: lower-triangle scatter-accumulate (rank_row >= rank_col)
    #pragma unroll
    for (int f = 0; f < 4; f++) {
        int rl0 = ti * TM + wm * 64 + f * 16 + (lane >> 2);
        #pragma unroll
        for (int a = 0; a < 2; a++) {
            int rl = rl0 + a * 8;
            if (rl >= cnt) continue;
            int gi = (seg == 0) ? rl : g_idx[seg][rl];
            float* rowp = &g_S[(size_t)gi * N];
            #pragma unroll
            for (int g = 0; g < 4; g++) {
                int cl = tj * TM + wn * 32 + g * 8 + 2 * (lane & 3);
                #pragma unroll
                for (int b2 = 0; b2 < 2; b2++) {
                    int c = cl + b2;
                    if (c < cnt && rl >= c) {
                        int gj = (seg == 0) ? c : g_idx[seg][c];
                        atomicAdd(rowp + gj, acc[f][g][a * 2 + b2]);
                    }
                }
            }
        }
    }
}

// ---------------------------------------------------------------------------
// Kernel 4: mirror lower triangle into upper (plain loads/stores, smem
// transpose). 64x64 tiles, 136 triangle blocks.
// ---------------------------------------------------------------------------
__global__ void k_mirror() {
    int b = blockIdx.x;                  // 0..135, tiles T=16
    int I = (int)((sqrtf(8.f * (float)b + 1.f) - 1.f) * 0.5f);
    while ((I + 1) * (I + 2) / 2 <= b) I++;
    while (I * (I + 1) / 2 > b) I--;
    int J = b - I * (I + 1) / 2;         // J <= I : source tile is lower

    __shared__ float tile[64][65];
    int tid = threadIdx.x;
    int r  = tid >> 4;                   // 0..15
    int c4 = tid & 15;                   // 0..15 -> col = c4*4

    #pragma unroll
    for (int q = 0; q < 4; q++) {
        int row = q * 16 + r;
        float4 v = *(const float4*)&g_S[(size_t)(I * 64 + row) * N + J * 64 + c4 * 4];
        tile[row][c4 * 4 + 0] = v.x;  tile[row][c4 * 4 + 1] = v.y;
        tile[row][c4 * 4 + 2] = v.z;  tile[row][c4 * 4 + 3] = v.w;
    }
    __syncthreads();

    // write S[J*64+row2][I*64+col2] = tile[col2][row2]
    #pragma unroll
    for (int q = 0; q < 4; q++) {
        int row2 = q * 16 + r;
        if (I != J) {
            float4 w = make_float4(tile[c4 * 4 + 0][row2], tile[c4 * 4 + 1][row2],
                                   tile[c4 * 4 + 2][row2], tile[c4 * 4 + 3][row2]);
            *(float4*)&g_S[(size_t)(J * 64 + row2) * N + I * 64 + c4 * 4] = w;
        } else {
            #pragma unroll
            for (int k = 0; k < 4; k++) {
                int col2 = c4 * 4 + k;
                if (col2 > row2)
                    g_S[(size_t)(J * 64 + row2) * N + I * 64 + col2] = tile[col2][row2];
            }
        }
    }
}

// ---------------------------------------------------------------------------
// Kernel 5: hard mining per row + fused mean accumulation into out.
// dist[i,j] = 0.5 - S[i,j] * rtab[O],  rtab[O] = 0.5/(O+1)  (no FDIV)
// ---------------------------------------------------------------------------
__global__ void k_mine(const int* __restrict__ lbl, float* __restrict__ out) {
    __shared__ float rtab[16];
    if (threadIdx.x < 9) rtab[threadIdx.x] = 0.5f / (float)(threadIdx.x + 1);
    __syncthreads();

    int i = blockIdx.x;
    int stride = g_lbl_stride;
    int li = lbl[(size_t)i * stride];
    unsigned mi = g_mask[i];

    float ap = -1e30f, an = 1e30f;
    #pragma unroll
    for (int u = 0; u < N / 256; u++) {
        int j = threadIdx.x + u * 256;
        float s = g_S[(size_t)i * N + j];
        int o = __popc(mi & g_mask[j]);
        float dist = 0.5f - s * rtab[o];
        if (lbl[(size_t)j * stride] == li) ap = fmaxf(ap, dist);
        else                               an = fminf(an, dist);
    }

    __shared__ float sap[256], san[256];
    sap[threadIdx.x] = ap;
    san[threadIdx.x] = an;
    __syncthreads();
    for (int o = 128; o; o >>= 1) {
        if (threadIdx.x < o) {
            sap[threadIdx.x] = fmaxf(sap[threadIdx.x], sap[threadIdx.x + o]);
            san[threadIdx.x] = fminf(san[threadIdx.x], san[threadIdx.x + o]);
        }
        __syncthreads();
    }
    if (threadIdx.x == 0)
        atomicAdd(out, fmaxf(0.f, sap[0] - san[0] + MARGIN) * (1.f / N));
}

// ---------------------------------------------------------------------------
extern "C" void kernel_launch(void* const* d_in, const int* in_sizes, int n_in,
                              void* d_out, int out_size) {
    const float* gf  = (const float*)d_in[0];   // global_feat  [N, D]
    const float* pf  = (const float*)d_in[1];   // partial_feat [N, P, D]
    const float* pl  = (const float*)d_in[2];   // part_labels  [N, P]
    const int*   lbl = (const int*)d_in[3];     // global_labels (int32 or int64)
    float* out = (float*)d_out;

    static int smem_set = 0;
    if (!smem_set) {
        cudaFuncSetAttribute(k_gemm_mma, cudaFuncAttributeMaxDynamicSharedMemorySize,
                             SMEM_TOTAL);
        smem_set = 1;
    }

    k_prep<<<N * SEG, 256>>>(gf, pf, pl, lbl, out);
    k_index<<<1, 256>>>();
    k_gemm_mma<<<dim3(SEG * NPAIR, KSPLIT), 256, SMEM_TOTAL>>>();
    k_mirror<<<136, 256>>>();
    k_mine<<<N, 256>>>(lbl, out);
}

// round 17
// speedup vs baseline: 20.4260x; 1.0275x over previous
#include <cuda_runtime.h>
#include <cuda_fp16.h>
#include <math.h>
#include <stdint.h>

// Problem constants
#define N    1024
#define P    8
#define D    2048
#define SEG  9                 // 1 global + 8 parts
#define MARGIN 0.3f

// GEMM tiling (per segment: K = D = 2048)
#define TM   128
#define TN   128
#define TK   64                // K elements per smem chunk (128B fp16 rows)
#define NTILE (N / TM)         // 8 tiles max per segment
#define NPAIR (NTILE * (NTILE + 1) / 2)   // 36 triangle pairs
#define KSPLIT 2
#define KPER  (D / KSPLIT)     // 1024
#define NCHUNK (KPER / TK)     // 16

// smem: per stage A tile (16KB) + B tile (16KB); 3 stages
#define TILE_B   (TM * TK * 2)         // 16384
#define STAGE_B  (2 * TILE_B)          // 32768
#define NSTAGE   3
#define SMEM_TOTAL (NSTAGE * STAGE_B)  // 98304

// Scratch (device globals: allocation-free rule)
__device__ __half    g_Hf[(size_t)SEG * N * D];  // per-segment fp16 features
__device__ float     g_S[(size_t)N * N];         // gram, LOWER triangle only
__device__ unsigned  g_mask[N];
__device__ int       g_idx[SEG][N];              // compacted row ids (parts)
__device__ int       g_cnt[SEG];
__device__ int       g_lbl_stride;   // 1 = int32 labels, 2 = int64 labels
__device__ unsigned  g_ap[N];        // encoded hardest-positive dist (max)
__device__ unsigned  g_an[N];        // encoded hardest-negative dist (min)

// ---------------------------------------------------------------------------
// Helpers
// ---------------------------------------------------------------------------
__device__ __forceinline__ uint32_t smem_u32(const void* p) {
    uint32_t a;
    asm("{ .reg .u64 t; cvta.to.shared.u64 t, %1; cvt.u32.u64 %0, t; }" : "=r"(a) : "l"(p));
    return a;
}
// order-preserving float<->uint encoding (monotone: enc(a)<enc(b) <=> a<b)
__device__ __forceinline__ unsigned encf(float f) {
    unsigned u = __float_as_uint(f);
    return (u >> 31) ? ~u : (u | 0x80000000u);
}
__device__ __forceinline__ float decf(unsigned k) {
    unsigned u = (k >> 31) ? (k & 0x7FFFFFFFu) : ~k;
    return __uint_as_float(u);
}
#define LDSM_X4(r0, r1, r2, r3, addr) \
    asm volatile("ldmatrix.sync.aligned.m8n8.x4.shared.b16 {%0,%1,%2,%3}, [%4];" \
        : "=r"(r0), "=r"(r1), "=r"(r2), "=r"(r3) : "r"(addr))
#define MMA16816(d, a0, a1, a2, a3, b0, b1) \
    asm volatile("mma.sync.aligned.m16n8k16.row.col.f32.f16.f16.f32 " \
        "{%0,%1,%2,%3}, {%4,%5,%6,%7}, {%8,%9}, {%0,%1,%2,%3};" \
        : "+f"((d)[0]), "+f"((d)[1]), "+f"((d)[2]), "+f"((d)[3]) \
        : "r"(a0), "r"(a1), "r"(a2), "r"(a3), "r"(b0), "r"(b1))
#define CP_ASYNC16(dst, src) \
    asm volatile("cp.async.cg.shared.global [%0], [%1], 16;" :: "r"(dst), "l"(src))
#define CP_COMMIT() asm volatile("cp.async.commit_group;" ::: "memory")
#define CP_WAIT1()  asm volatile("cp.async.wait_group 1;" ::: "memory")
// packed fp32x2 reduction (sm_90 base ISA; compiles for plain compute_103)
__device__ __forceinline__ void red2(float* p, float x, float y) {
    asm volatile("red.global.add.v2.f32 [%0], {%1, %2};"
                 :: "l"(p), "f"(x), "f"(y) : "memory");
}

// ---------------------------------------------------------------------------
// Kernel 1: prep — normalize + fp16 pack (float2 in, half2 out), fused with
// g_S zeroing, ap/an init, part-mask packing, label-dtype detect.
// Part segments with label==0 are skipped entirely (never read by the GEMM).
// ---------------------------------------------------------------------------
__global__ void k_prep(const float* __restrict__ gf,
                       const float* __restrict__ pf,
                       const float* __restrict__ pl,
                       const int* __restrict__ lbl) {
    int b = blockIdx.x;                  // 0 .. N*SEG-1
    int i = b / SEG;
    int s = b % SEG;

    // fused: blocks 0..N-1 zero one row of g_S + init mining accumulators
    if (b < N) {
        *(float4*)&g_S[(size_t)b * N + (size_t)threadIdx.x * 4] =
            make_float4(0.f, 0.f, 0.f, 0.f);
        if (threadIdx.x == 0) {
            g_ap[b] = encf(-1e30f);
            g_an[b] = encf(1e30f);
        }
    }

    if (s == 0 && threadIdx.x == 0) {
        unsigned m = 0;
        #pragma unroll
        for (int k = 0; k < P; k++)
            if (pl[(size_t)i * P + k] != 0.f) m |= (1u << k);
        g_mask[i] = m;
    }
    if (b == 0 && threadIdx.x >= 32 && threadIdx.x < 64) {
        int lane = threadIdx.x - 32;
        int v = 0;
        for (int j = 1 + 2 * lane; j < N; j += 64) v |= lbl[j];
        #pragma unroll
        for (int o = 16; o; o >>= 1) v |= __shfl_xor_sync(0xffffffffu, v, o);
        if (lane == 0) g_lbl_stride = v ? 1 : 2;
    }

    float plv = 1.f;
    if (s > 0) {
        plv = pl[(size_t)i * P + (s - 1)];
        if (plv == 0.f) return;          // zero segment: never read downstream
    }
    const float2* src = (const float2*)((s == 0) ? (gf + (size_t)i * D)
                                : (pf + ((size_t)i * P + (s - 1)) * D));

    float2 vals[4];
    float ss = 0.f;
    #pragma unroll
    for (int u = 0; u < 4; u++) {
        float2 v = src[threadIdx.x + 256 * u];
        vals[u] = v;
        ss += v.x * v.x + v.y * v.y;
    }
    __shared__ float red[8];
    #pragma unroll
    for (int o = 16; o; o >>= 1) ss += __shfl_xor_sync(0xffffffffu, ss, o);
    if ((threadIdx.x & 31) == 0) red[threadIdx.x >> 5] = ss;
    __syncthreads();
    if (threadIdx.x < 8) {
        float v = red[threadIdx.x];
        #pragma unroll
        for (int o = 4; o; o >>= 1) v += __shfl_xor_sync(0xffu, v, o);
        if (threadIdx.x == 0) red[0] = v;
    }
    __syncthreads();

    float scale = plv / (sqrtf(red[0]) + 1e-12f);
    __half2* dst = (__half2*)(g_Hf + ((size_t)s * N + i) * D);
    #pragma unroll
    for (int u = 0; u < 4; u++)
        dst[threadIdx.x + 256 * u] =
            __floats2half2_rn(vals[u].x * scale, vals[u].y * scale);
}

// ---------------------------------------------------------------------------
// Kernel 2: build compacted row-index lists per part (warp w -> part w)
// ---------------------------------------------------------------------------
__global__ void k_index() {
    int lane = threadIdx.x & 31;
    int w    = threadIdx.x >> 5;         // part 0..7 -> segment w+1
    unsigned total = 0;
    for (int c = 0; c < N / 32; c++) {
        int row = c * 32 + lane;
        int bit = (g_mask[row] >> w) & 1;
        unsigned bal = __ballot_sync(0xffffffffu, bit);
        if (bit)
            g_idx[w + 1][total + __popc(bal & ((1u << lane) - 1u))] = row;
        total += __popc(bal);
    }
    if (lane == 0) g_cnt[w + 1] = (int)total;
}

// ---------------------------------------------------------------------------
// Kernel 3: HMMA fp16 GEMM over compacted per-segment row sets.
// Lower-triangle epilogue. seg0 uses packed red.v2.f32 (contiguous cols);
// part segments use scalar REDs (scattered cols). Stray upper-adjacent pair
// writes on seg0 diagonal land in slots k_tile never reads.
// ---------------------------------------------------------------------------
__global__ void __launch_bounds__(256, 2) k_gemm_mma() {
    extern __shared__ char smem[];
    uint32_t sbase = smem_u32(smem);

    int tid  = threadIdx.x;
    int lane = tid & 31;
    int wid  = tid >> 5;
    int wm   = wid >> 2;      // 0..1  (M warp row)
    int wn   = wid & 3;       // 0..3  (N warp col)

    int seg = blockIdx.x / NPAIR;
    int pid = blockIdx.x % NPAIR;
    int ti = (int)((sqrtf(8.f * (float)pid + 1.f) - 1.f) * 0.5f);
    while ((ti + 1) * (ti + 2) / 2 <= pid) ti++;
    while (ti * (ti + 1) / 2 > pid) ti--;
    int tj = pid - ti * (ti + 1) / 2;     // tj <= ti

    int cnt = (seg == 0) ? N : g_cnt[seg];
    if (ti >= ((cnt + TM - 1) >> 7)) return;   // tile beyond row count

    int kbase = blockIdx.y * KPER;
    const __half* segbase = g_Hf + (size_t)seg * N * D;

    // gather offsets (elements) for cp.async: 4 rows each for A and B
    int rA  = tid >> 3;        // 0..31 (+32 per q)
    int c16 = tid & 7;
    uint32_t offA[4], offB[4];
    #pragma unroll
    for (int q = 0; q < 4; q++) {
        int ga = ti * TM + rA + 32 * q;
        int gb = tj * TM + rA + 32 * q;
        int ia = (seg == 0) ? ga : g_idx[seg][min(ga, cnt - 1)];
        int ib = (seg == 0) ? gb : g_idx[seg][min(gb, cnt - 1)];
        offA[q] = (uint32_t)(ia * D + c16 * 8);
        offB[q] = (uint32_t)(ib * D + c16 * 8);
    }
    uint32_t pso = (uint32_t)(rA * 128 + ((c16 ^ (rA & 7)) << 4));

    // ldmatrix bases; fragment rows are multiples of 8 -> XOR operand lane&7
    uint32_t r7 = (uint32_t)(lane & 7);
    uint32_t aBase[4];
    #pragma unroll
    for (int f = 0; f < 4; f++)
        aBase[f] = sbase + (uint32_t)((wm * 64 + f * 16 + (lane & 15)) * 128);
    uint32_t aHalf = (uint32_t)(lane >> 4);
    uint32_t bBase[2];
    #pragma unroll
    for (int gp = 0; gp < 2; gp++)
        bBase[gp] = sbase + TILE_B +
            (uint32_t)((wn * 32 + gp * 16 + ((lane >> 4) << 3) + (lane & 7)) * 128);
    uint32_t bHalf = (uint32_t)((lane >> 3) & 1);

    float acc[4][4][4];
    #pragma unroll
    for (int i = 0; i < 4; i++)
        #pragma unroll
        for (int j = 0; j < 4; j++)
            #pragma unroll
            for (int e = 0; e < 4; e++) acc[i][j][e] = 0.f;

    auto issue = [&](int t) {
        if (t < NCHUNK) {
            uint32_t st = (uint32_t)(t % NSTAGE) * STAGE_B;
            uint32_t dA = sbase + st + pso;
            uint32_t dB = dA + TILE_B;
            const __half* sk = segbase + kbase + t * TK;
            #pragma unroll
            for (int q = 0; q < 4; q++) {
                CP_ASYNC16(dA + q * 4096, sk + offA[q]);
                CP_ASYNC16(dB + q * 4096, sk + offB[q]);
            }
        }
        CP_COMMIT();
    };

    issue(0);
    issue(1);

    for (int t = 0; t < NCHUNK; t++) {
        CP_WAIT1();
        __syncthreads();
        issue(t + 2);            // overwrites stage (t-1)%3: consumed pre-sync

        uint32_t boff = (uint32_t)(t % NSTAGE) * STAGE_B;
        #pragma unroll
        for (int s = 0; s < 4; s++) {              // 4 k16 steps per chunk
            uint32_t swA = ((2u * s + aHalf) ^ r7) << 4;
            uint32_t swB = ((2u * s + bHalf) ^ r7) << 4;
            uint32_t af[4][4];
            #pragma unroll
            for (int f = 0; f < 4; f++)
                LDSM_X4(af[f][0], af[f][1], af[f][2], af[f][3],
                        aBase[f] + boff + swA);
            uint32_t bf[4][2];
            #pragma unroll
            for (int gp = 0; gp < 2; gp++) {
                uint32_t r0, r1, r2, r3;
                LDSM_X4(r0, r1, r2, r3, bBase[gp] + boff + swB);
                bf[gp * 2][0] = r0;     bf[gp * 2][1] = r1;
                bf[gp * 2 + 1][0] = r2; bf[gp * 2 + 1][1] = r3;
            }
            #pragma unroll
            for (int f = 0; f < 4; f++)
                #pragma unroll
                for (int g = 0; g < 4; g++)
                    MMA16816(acc[f][g], af[f][0], af[f][1], af[f][2], af[f][3],
                             bf[g][0], bf[g][1]);
        }
    }

    // epilogue: lower-triangle scatter-accumulate
    if (seg == 0) {
        #pragma unroll
        for (int f = 0; f < 4; f++) {
            int rl0 = ti * TM + wm * 64 + f * 16 + (lane >> 2);
            #pragma unroll
            for (int a = 0; a < 2; a++) {
                int rl = rl0 + a * 8;
                float* rowp = &g_S[(size_t)rl * N];
                #pragma unroll
                for (int g = 0; g < 4; g++) {
                    int c = tj * TM + wn * 32 + g * 8 + 2 * (lane & 3);
                    if (rl >= c)   // pair write; (rl,rl+1) stray is never read
                        red2(rowp + c, acc[f][g][a * 2], acc[f][g][a * 2 + 1]);
                }
            }
        }
    } else {
        #pragma unroll
        for (int f = 0; f < 4; f++) {
            int rl0 = ti * TM + wm * 64 + f * 16 + (lane >> 2);
            #pragma unroll
            for (int a = 0; a < 2; a++) {
                int rl = rl0 + a * 8;
                if (rl >= cnt) continue;
                int gi = g_idx[seg][rl];
                float* rowp = &g_S[(size_t)gi * N];
                #pragma unroll
                for (int g = 0; g < 4; g++) {
                    int cl = tj * TM + wn * 32 + g * 8 + 2 * (lane & 3);
                    #pragma unroll
                    for (int b2 = 0; b2 < 2; b2++) {
                        int c = cl + b2;
                        if (c < cnt && rl >= c)
                            atomicAdd(rowp + g_idx[seg][c], acc[f][g][a * 2 + b2]);
                    }
                }
            }
        }
    }
}

// ---------------------------------------------------------------------------
// Kernel 4: tile-based hard mining on the LOWER triangle.
// Each 64x64 tile (I>=J) contributes: row-band reductions (rows of S) and
// col-band reductions (mirrored rows) via encoded atomicMax/atomicMin.
// Diagonal tiles read dt[max(r,c)][min(r,c)] (upper entries never touched).
// ---------------------------------------------------------------------------
__global__ void k_tile(const int* __restrict__ lbl) {
    __shared__ float    dt[64][65];
    __shared__ int      lblI[64], lblJ[64];
    __shared__ unsigned mI[64], mJ[64];
    __shared__ float    rtab[16];

    int b = blockIdx.x;                  // 0..135
    int I = (int)((sqrtf(8.f * (float)b + 1.f) - 1.f) * 0.5f);
    while ((I + 1) * (I + 2) / 2 <= b) I++;
    while (I * (I + 1) / 2 > b) I--;
    int J = b - I * (I + 1) / 2;         // J <= I

    int tid = threadIdx.x;
    int stride = g_lbl_stride;
    if (tid < 64) {
        lblI[tid] = lbl[(size_t)(I * 64 + tid) * stride];
        mI[tid]   = g_mask[I * 64 + tid];
    } else if (tid < 128) {
        int c = tid - 64;
        lblJ[c] = lbl[(size_t)(J * 64 + c) * stride];
        mJ[c]   = g_mask[J * 64 + c];
    }
    if (tid < 9) rtab[tid] = 0.5f / (float)(tid + 1);

    // load raw S tile (float4)
    int r0 = tid >> 4, c4 = tid & 15;
    #pragma unroll
    for (int q = 0; q < 4; q++) {
        int row = q * 16 + r0;
        float4 v = *(const float4*)&g_S[(size_t)(I * 64 + row) * N + J * 64 + c4 * 4];
        dt[row][c4 * 4 + 0] = v.x;  dt[row][c4 * 4 + 1] = v.y;
        dt[row][c4 * 4 + 2] = v.z;  dt[row][c4 * 4 + 3] = v.w;
    }
    __syncthreads();

    // convert to dist in place
    #pragma unroll
    for (int q = 0; q < 4; q++) {
        int row = q * 16 + r0;
        #pragma unroll
        for (int k = 0; k < 4; k++) {
            int col = c4 * 4 + k;
            dt[row][col] = 0.5f - dt[row][col] * rtab[__popc(mI[row] & mJ[col])];
        }
    }
    __syncthreads();

    if (tid < 64) {                      // row-band reduction: row r of S
        int r = tid, L = lblI[r];
        float ap = -1e30f, an = 1e30f;
        #pragma unroll 8
        for (int c = 0; c < 64; c++) {
            float v = (I == J) ? dt[max(r, c)][min(r, c)] : dt[r][c];
            if (lblJ[c] == L) ap = fmaxf(ap, v);
            else              an = fminf(an, v);
        }
        atomicMax(&g_ap[I * 64 + r], encf(ap));
        atomicMin(&g_an[I * 64 + r], encf(an));
    } else if (tid < 128 && I != J) {    // col-band reduction: mirrored rows
        int c = tid - 64, L = lblJ[c];
        float ap = -1e30f, an = 1e30f;
        #pragma unroll 8
        for (int r = 0; r < 64; r++) {
            float v = dt[r][c];
            if (lblI[r] == L) ap = fmaxf(ap, v);
            else              an = fminf(an, v);
        }
        atomicMax(&g_ap[J * 64 + c], encf(ap));
        atomicMin(&g_an[J * 64 + c], encf(an));
    }
}

// ---------------------------------------------------------------------------
// Kernel 5: final loss = mean(relu(ap - an + margin))
// ---------------------------------------------------------------------------
__global__ void k_loss(float* __restrict__ out) {
    float s = 0.f;
    #pragma unroll
    for (int u = 0; u < N / 256; u++) {
        int i = threadIdx.x + u * 256;
        s += fmaxf(0.f, decf(g_ap[i]) - decf(g_an[i]) + MARGIN);
    }
    __shared__ float red[8];
    #pragma unroll
    for (int o = 16; o; o >>= 1) s += __shfl_xor_sync(0xffffffffu, s, o);
    if ((threadIdx.x & 31) == 0) red[threadIdx.x >> 5] = s;
    __syncthreads();
    if (threadIdx.x == 0) {
        float t = 0.f;
        #pragma unroll
        for (int w = 0; w < 8; w++) t += red[w];
        out[0] = t / (float)N;
    }
}

// ---------------------------------------------------------------------------
extern "C" void kernel_launch(void* const* d_in, const int* in_sizes, int n_in,
                              void* d_out, int out_size) {
    const float* gf  = (const float*)d_in[0];   // global_feat  [N, D]
    const float* pf  = (const float*)d_in[1];   // partial_feat [N, P, D]
    const float* pl  = (const float*)d_in[2];   // part_labels  [N, P]
    const int*   lbl = (const int*)d_in[3];     // global_labels (int32 or int64)
    float* out = (float*)d_out;

    static int smem_set = 0;
    if (!smem_set) {
        cudaFuncSetAttribute(k_gemm_mma, cudaFuncAttributeMaxDynamicSharedMemorySize,
                             SMEM_TOTAL);
        smem_set = 1;
    }

    k_prep<<<N * SEG, 256>>>(gf, pf, pl, lbl);
    k_index<<<1, 256>>>();
    k_gemm_mma<<<dim3(SEG * NPAIR, KSPLIT), 256, SMEM_TOTAL>>>();
    k_tile<<<136, 256>>>(lbl);
    k_loss<<<1, 256>>>(out);
}